// round 13
// baseline (speedup 1.0000x reference)
#include <cuda_runtime.h>
#include <cuda_fp16.h>
#include <math.h>

// ---------------------------------------------------------------------------
// Static scratch (allocation-free per harness rules)
// ---------------------------------------------------------------------------
#define N2MAX 1536
#define G2MAX (8*N2MAX)
#define U1MAX 15872
#define G1MAX (8*U1MAX)
#define U0MAX 160256

__device__ float g_acc2[(N2MAX+1)*128];
__device__ float g_accg2[((size_t)G2MAX+1)*128];
__device__ float g_acc1[((size_t)U1MAX+1)*128];
__device__ float g_accg1[((size_t)G1MAX+1)*64];
__device__ float g_acc0[((size_t)U0MAX+1)*128];
__device__ float g_stats[8*256];

// fp16 GEMM inputs
__device__ __half g_f2h[(size_t)N2MAX*256];
__device__ __half g_tg2h[(size_t)G2MAX*128];
__device__ __half g_x1h[(size_t)U1MAX*128];
__device__ __half g_t1h[(size_t)G1MAX*64];
__device__ __half g_x0h[(size_t)U0MAX*64];
// fp16 weights, n-major [tap][cout][cin]
__device__ __half g_wh[2428928];

#define O_WOUT0 0
#define O_WOUT1 221184
#define O_WOUT2 663552
#define O_WT2   1548288
#define O_WU2   1810432
#define O_WT1   2252800
#define O_WU1   2318336

#define ASTRH 72   // smem row stride in halves (144B): ldsm conflict-free, 16B-aligned

__device__ __forceinline__ unsigned smem_u32(const void* p) {
    unsigned a;
    asm("{ .reg .u64 t; cvta.to.shared.u64 t, %1; cvt.u32.u64 %0, t; }" : "=r"(a) : "l"(p));
    return a;
}
__device__ __forceinline__ void cp_async16z(void* sdst, const void* gsrc, int bytes) {
    unsigned saddr = smem_u32(sdst);
    asm volatile("cp.async.cg.shared.global [%0], [%1], 16, %2;"
                 :: "r"(saddr), "l"(gsrc), "r"(bytes));
}
__device__ __forceinline__ void cp_async16(void* sdst, const void* gsrc) {
    unsigned saddr = smem_u32(sdst);
    asm volatile("cp.async.cg.shared.global [%0], [%1], 16;" :: "r"(saddr), "l"(gsrc));
}
__device__ __forceinline__ void cp_commit_wait() {
    asm volatile("cp.async.commit_group;\n\tcp.async.wait_group 0;" ::: "memory");
}
__device__ __forceinline__ void ldsm_x4(unsigned& r0, unsigned& r1,
                                        unsigned& r2, unsigned& r3, const void* p)
{
    unsigned addr = smem_u32(p);
    asm volatile("ldmatrix.sync.aligned.m8n8.x4.shared.b16 {%0,%1,%2,%3}, [%4];"
                 : "=r"(r0), "=r"(r1), "=r"(r2), "=r"(r3) : "r"(addr));
}
__device__ __forceinline__ void mma_f16(float& c0, float& c1, float& c2, float& c3,
                                        unsigned a0, unsigned a1, unsigned a2, unsigned a3,
                                        unsigned b0, unsigned b1)
{
    asm volatile("mma.sync.aligned.m16n8k16.row.col.f32.f16.f16.f32 "
                 "{%0,%1,%2,%3},{%4,%5,%6,%7},{%8,%9},{%0,%1,%2,%3};"
                 : "+f"(c0), "+f"(c1), "+f"(c2), "+f"(c3)
                 : "r"(a0), "r"(a1), "r"(a2), "r"(a3), "r"(b0), "r"(b1));
}
__device__ __forceinline__ void red_add_v2(float* p, float a, float b) {
    asm volatile("red.global.add.v2.f32 [%0], {%1,%2};"
                 :: "l"(p), "f"(a), "f"(b) : "memory");
}

// ---------------------------------------------------------------------------
// GEMM body: 128 x TN x cin fp16, chunked by 64 k. (unchanged from R12)
// ---------------------------------------------------------------------------
template<int TN>
__device__ __forceinline__ void gemm_body(
    const __half* __restrict__ X, const __half* __restrict__ Wt,
    const int* gidx, __half (*Asm)[ASTRH], __half (*Bsm)[ASTRH],
    int cin, int tid, int wm, int wn, int lane, float (&c)[2][TN/16][4])
{
    constexpr int NI = TN / 16;
    const int ar  = tid >> 1;
    const int as0 = (tid & 1) * 4;
    const int g = gidx[ar];
    const __half* asrc = X + (size_t)(g >= 0 ? g : 0) * cin;
    const int abytes = (g >= 0) ? 16 : 0;
    const int lr = lane & 15;
    const int koff = (lane >> 4) * 8;

    for (int kc = 0; kc < cin; kc += 64) {
        if (kc) __syncthreads();
        #pragma unroll
        for (int j = 0; j < 4; j++) {
            const int seg = as0 + j;
            cp_async16z(&Asm[ar][seg * 8], asrc + kc + seg * 8, abytes);
        }
        #pragma unroll
        for (int l = 0; l < TN / 32; l++) {
            const int idx = tid + l * 256;
            const int nn = idx >> 3, seg = idx & 7;
            cp_async16(&Bsm[nn][seg * 8], Wt + (size_t)nn * cin + kc + seg * 8);
        }
        cp_commit_wait();
        __syncthreads();

        #pragma unroll
        for (int kt = 0; kt < 4; kt++) {
            const int kb = kt * 16 + koff;
            unsigned a[2][4];
            #pragma unroll
            for (int mi = 0; mi < 2; mi++)
                ldsm_x4(a[mi][0], a[mi][1], a[mi][2], a[mi][3],
                        &Asm[wm + mi * 16 + lr][kb]);
            unsigned b[NI][2];
            #pragma unroll
            for (int nj = 0; nj < NI / 2; nj++) {
                unsigned r0, r1, r2, r3;
                ldsm_x4(r0, r1, r2, r3, &Bsm[wn + nj * 16 + lr][kb]);
                b[2*nj][0] = r0; b[2*nj+1][0] = r1;
                b[2*nj][1] = r2; b[2*nj+1][1] = r3;
            }
            #pragma unroll
            for (int mi = 0; mi < 2; mi++)
                #pragma unroll
                for (int ni = 0; ni < NI; ni++)
                    mma_f16(c[mi][ni][0], c[mi][ni][1], c[mi][ni][2], c[mi][ni][3],
                            a[mi][0], a[mi][1], a[mi][2], a[mi][3], b[ni][0], b[ni][1]);
        }
    }
}

// ---------------------------------------------------------------------------
// Scatter-style tap conv (fp16 HMMA + fp32 RED). grid = (ceil(n/128), 27)
// ---------------------------------------------------------------------------
template<int TN, int MAXCTA>
__global__ __launch_bounds__(256, MAXCTA) void conv3(
    const __half* __restrict__ X, const __half* __restrict__ W27,
    float* __restrict__ C, const int* __restrict__ maps,
    int Mpad, int n, int cin)
{
    constexpr int NI = TN / 16;
    __shared__ __align__(16) __half Asm[128][ASTRH];
    __shared__ __align__(16) __half Bsm[TN][ASTRH];
    __shared__ int gidx[128], sidx[128];

    const int z    = blockIdx.y;
    const int Mz   = (z == 26) ? n : Mpad;
    const int row0 = blockIdx.x * 128;
    if (row0 >= Mz) return;

    const int tap  = (z == 26) ? 13 : ((z < 13) ? z : z + 1);
    const __half* Wt = W27 + (size_t)tap * cin * TN;
    const int tid  = threadIdx.x;
    const int scrap = n;

    int myvalid = 0;
    if (tid < 128) {
        int r = row0 + tid;
        int g = -1, s = -1;
        if (r < Mz) {
            if (z == 26) { g = r; s = r; }
            else {
                g = maps[(size_t)z * Mpad + r];
                s = maps[(size_t)(26 + z) * Mpad + r];
            }
        }
        gidx[tid] = g;
        sidx[tid] = s;
        myvalid = (s >= 0 && s != scrap);
    }
    if (__syncthreads_count(myvalid) == 0) return;

    const int lane = tid & 31;
    const int warp = tid >> 5;
    const int wm = (warp & 3) * 32;
    const int wn = (warp >> 2) * (TN / 2);

    float c[2][NI][4];
    #pragma unroll
    for (int mi = 0; mi < 2; mi++)
        #pragma unroll
        for (int ni = 0; ni < NI; ni++)
            #pragma unroll
            for (int j = 0; j < 4; j++) c[mi][ni][j] = 0.f;

    gemm_body<TN>(X, Wt, gidx, Asm, Bsm, cin, tid, wm, wn, lane, c);

    const int qr = lane >> 2, qc = lane & 3;
    #pragma unroll
    for (int mi = 0; mi < 2; mi++) {
        #pragma unroll
        for (int half_ = 0; half_ < 2; half_++) {
            const int lr2 = wm + mi * 16 + qr + half_ * 8;
            const int o = sidx[lr2];
            if (o < 0 || o == scrap) continue;
            float* cp = C + (size_t)o * TN + wn + qc * 2;
            #pragma unroll
            for (int ni = 0; ni < NI; ni++)
                red_add_v2(cp + ni * 8, c[mi][ni][half_*2], c[mi][ni][half_*2+1]);
        }
    }
}

// ---------------------------------------------------------------------------
// Batched transpose conv (fp16 in, fp16 out): T[z*n + r] = X[r] @ Wt[z]
// ---------------------------------------------------------------------------
template<int TN, int MAXCTA>
__global__ __launch_bounds__(256, MAXCTA) void tconv3(
    const __half* __restrict__ X, const __half* __restrict__ W8,
    __half* __restrict__ T, int n, int cin)
{
    constexpr int NI = TN / 16;
    __shared__ __align__(16) __half Asm[128][ASTRH];
    __shared__ __align__(16) __half Bsm[TN][ASTRH];
    __shared__ int gidx[128];

    const int z    = blockIdx.y;
    const int row0 = blockIdx.x * 128;
    if (row0 >= n) return;
    const __half* Wt = W8 + (size_t)z * cin * TN;
    const int tid  = threadIdx.x;

    if (tid < 128) {
        int r = row0 + tid;
        gidx[tid] = (r < n) ? r : -1;
    }
    __syncthreads();

    const int lane = tid & 31;
    const int warp = tid >> 5;
    const int wm = (warp & 3) * 32;
    const int wn = (warp >> 2) * (TN / 2);

    float c[2][NI][4];
    #pragma unroll
    for (int mi = 0; mi < 2; mi++)
        #pragma unroll
        for (int ni = 0; ni < NI; ni++)
            #pragma unroll
            for (int j = 0; j < 4; j++) c[mi][ni][j] = 0.f;

    gemm_body<TN>(X, Wt, gidx, Asm, Bsm, cin, tid, wm, wn, lane, c);

    const int qr = lane >> 2, qc = lane & 3;
    #pragma unroll
    for (int mi = 0; mi < 2; mi++) {
        #pragma unroll
        for (int half_ = 0; half_ < 2; half_++) {
            const int r = row0 + wm + mi * 16 + qr + half_ * 8;
            if (r >= n) continue;
            __half* tp = T + ((size_t)z * n + r) * TN + wn + qc * 2;
            #pragma unroll
            for (int ni = 0; ni < NI; ni++) {
                __half2 hv = __floats2half2_rn(c[mi][ni][half_*2], c[mi][ni][half_*2+1]);
                *reinterpret_cast<__half2*>(tp + ni * 8) = hv;
            }
        }
    }
}

// ---------------------------------------------------------------------------
// One-shot converters (vectorized)
// ---------------------------------------------------------------------------
__global__ void build_wh(const float* __restrict__ src, __half* __restrict__ dst,
                         long long total, int cin, int cout)
{
    long long i = (long long)blockIdx.x * blockDim.x + threadIdx.x;
    if (i >= total) return;
    const long long per = (long long)cin * cout;
    const int t = (int)(i / per);
    const int rem = (int)(i % per);
    const int k = rem / cout, nn = rem % cout;
    dst[(long long)t * per + (long long)nn * cin + k] = __float2half(src[i]);
}

__global__ void f2h4(const float* __restrict__ src, __half* __restrict__ dst, long long n4)
{
    long long i = (long long)blockIdx.x * blockDim.x + threadIdx.x;
    if (i >= n4) return;
    float4 v = ((const float4*)src)[i];
    __half2 h0 = __floats2half2_rn(v.x, v.y);
    __half2 h1 = __floats2half2_rn(v.z, v.w);
    ((uint2*)dst)[i] = make_uint2(*(unsigned*)&h0, *(unsigned*)&h1);
}

// ---------------------------------------------------------------------------
// BatchNorm (training-mode batch stats) + ELU -- vectorized
// ---------------------------------------------------------------------------
template<typename T>
__global__ void bn_stats(const T* __restrict__ X, int n, int c, int rpb,
                         float* __restrict__ stats)
{
    // each thread covers 2 channels via vector load
    const int c2 = c >> 1;
    const int tpr = blockDim.x / c2;
    const int ch2 = threadIdx.x % c2;
    const int rg = threadIdx.x / c2;
    const int r0 = blockIdx.x * rpb;
    int rend = r0 + rpb; if (rend > n) rend = n;
    float s0 = 0.f, sq0 = 0.f, s1 = 0.f, sq1 = 0.f;
    for (int r = r0 + rg; r < rend; r += tpr) {
        float v0, v1;
        if (sizeof(T) == 2) {
            __half2 h = *(const __half2*)((const __half*)X + (size_t)r * c + ch2 * 2);
            v0 = __low2float(h); v1 = __high2float(h);
        } else {
            float2 f = *(const float2*)((const float*)X + (size_t)r * c + ch2 * 2);
            v0 = f.x; v1 = f.y;
        }
        s0 += v0; sq0 += v0 * v0;
        s1 += v1; sq1 += v1 * v1;
    }
    atomicAdd(&stats[ch2*2],       s0);
    atomicAdd(&stats[ch2*2+1],     s1);
    atomicAdd(&stats[c + ch2*2],   sq0);
    atomicAdd(&stats[c + ch2*2+1], sq1);
}

// final output: fp32 acc -> fp32 out (float4)
__global__ void bn_apply_ff(const float* __restrict__ X, float* __restrict__ Y,
                            const float* __restrict__ stats,
                            const float* __restrict__ gb, long long total4, int n, int c)
{
    long long i = (long long)blockIdx.x * blockDim.x + threadIdx.x;
    if (i >= total4) return;
    const float inv_n = 1.f / (float)n;
    const int ch0 = (int)((i * 4) % c);
    float4 x = ((const float4*)X)[i];
    float4 y;
    #pragma unroll
    for (int j = 0; j < 4; j++) {
        const int ch = ch0 + j;
        float mu  = stats[ch] * inv_n;
        float var = stats[c + ch] * inv_n - mu * mu;
        float xv = (&x.x)[j];
        float v = gb[ch] * (xv - mu) * rsqrtf(var + 1e-5f) + gb[c + ch];
        (&y.x)[j] = (v > 0.f) ? v : expm1f(v);
    }
    ((float4*)Y)[i] = y;
}

// intermediate: fp16 in-place (half2)
__global__ void bn_apply_hh(const __half* __restrict__ X, __half* __restrict__ Y,
                            const float* __restrict__ stats,
                            const float* __restrict__ gb, long long total2, int n, int c)
{
    long long i = (long long)blockIdx.x * blockDim.x + threadIdx.x;
    if (i >= total2) return;
    const float inv_n = 1.f / (float)n;
    const int ch0 = (int)((i * 2) % c);
    __half2 h = ((const __half2*)X)[i];
    float xv0 = __low2float(h), xv1 = __high2float(h);
    float mu0  = stats[ch0] * inv_n;
    float var0 = stats[c + ch0] * inv_n - mu0 * mu0;
    float v0 = gb[ch0] * (xv0 - mu0) * rsqrtf(var0 + 1e-5f) + gb[c + ch0];
    v0 = (v0 > 0.f) ? v0 : expm1f(v0);
    float mu1  = stats[ch0+1] * inv_n;
    float var1 = stats[c + ch0+1] * inv_n - mu1 * mu1;
    float v1 = gb[ch0+1] * (xv1 - mu1) * rsqrtf(var1 + 1e-5f) + gb[c + ch0+1];
    v1 = (v1 > 0.f) ? v1 : expm1f(v1);
    ((__half2*)Y)[i] = __floats2half2_rn(v0, v1);
}

// fused: DSTh[idx[r]] += elu(bn(ACC[r]))  (half2)
__global__ void bn_apply_add(const float* __restrict__ ACC, __half* __restrict__ DST,
                             const int* __restrict__ idx,
                             const float* __restrict__ stats,
                             const float* __restrict__ gb, long long total2, int n, int c)
{
    long long i = (long long)blockIdx.x * blockDim.x + threadIdx.x;
    if (i >= total2) return;
    const float inv_n = 1.f / (float)n;
    const long long e = i * 2;
    const int r = (int)(e / c), ch0 = (int)(e % c);
    float2 x = ((const float2*)ACC)[i];
    float mu0  = stats[ch0] * inv_n;
    float var0 = stats[c + ch0] * inv_n - mu0 * mu0;
    float v0 = gb[ch0] * (x.x - mu0) * rsqrtf(var0 + 1e-5f) + gb[c + ch0];
    v0 = (v0 > 0.f) ? v0 : expm1f(v0);
    float mu1  = stats[ch0+1] * inv_n;
    float var1 = stats[c + ch0+1] * inv_n - mu1 * mu1;
    float v1 = gb[ch0+1] * (x.y - mu1) * rsqrtf(var1 + 1e-5f) + gb[c + ch0+1];
    v1 = (v1 > 0.f) ? v1 : expm1f(v1);
    __half2* p = (__half2*)(DST + (size_t)idx[r] * c + ch0);
    __half2 old = *p;
    *p = __floats2half2_rn(__low2float(old) + v0, __high2float(old) + v1);
}

// scatter: dsth[idx[r]] = f2h(src[r])  (4 elems)
__global__ void scatter_copy_f2h4(const float* __restrict__ src, __half* __restrict__ dst,
                                  const int* __restrict__ idx, long long total4, int c)
{
    long long i = (long long)blockIdx.x * blockDim.x + threadIdx.x;
    if (i >= total4) return;
    const long long e = i * 4;
    const int r = (int)(e / c), ch = (int)(e % c);
    float4 v = ((const float4*)src)[i];
    __half2 h0 = __floats2half2_rn(v.x, v.y);
    __half2 h1 = __floats2half2_rn(v.z, v.w);
    *(uint2*)(dst + (size_t)idx[r] * c + ch) = make_uint2(*(unsigned*)&h0, *(unsigned*)&h1);
}

// ---------------------------------------------------------------------------
// Host-side orchestration
// ---------------------------------------------------------------------------
static void wh_launch(const float* src, __half* dst, int taps, int cin, int cout,
                      cudaStream_t st)
{
    long long total = (long long)taps * cin * cout;
    build_wh<<<(unsigned)((total + 255) / 256), 256, 0, st>>>(src, dst, total, cin, cout);
}

static void sconv3_launch(const __half* X, const __half* W27, const int* m,
                          int n, int Mpad, int cin, int cout, float* acc,
                          cudaStream_t st)
{
    dim3 grid((n + 127) / 128, 27);
    if (cout == 128)
        conv3<128, 2><<<grid, 256, 0, st>>>(X, W27, acc, m, Mpad, n, cin);
    else
        conv3<64, 3><<<grid, 256, 0, st>>>(X, W27, acc, m, Mpad, n, cin);
}

static void tconv_launch(const __half* X, const __half* W8, __half* T,
                         int n, int cin, int cout, cudaStream_t st)
{
    dim3 grid((n + 127) / 128, 8);
    if (cout == 128)
        tconv3<128, 2><<<grid, 256, 0, st>>>(X, W8, T, n, cin);
    else
        tconv3<64, 3><<<grid, 256, 0, st>>>(X, W8, T, n, cin);
}

template<typename T>
static void bn_stats_launch(const T* X, int n, int c, float* stats, cudaStream_t st)
{
    const int rpb = (n >= 16384) ? 128 : 32;
    const int c2 = c / 2;
    bn_stats<T><<<(n + rpb - 1) / rpb, c2 * (256 / c2), 0, st>>>(X, n, c, rpb, stats);
}

static void bn_elu_ff(const float* X, float* Y, const float* gb,
                      int n, int c, float* stats, cudaStream_t st)
{
    bn_stats_launch<float>(X, n, c, stats, st);
    long long t4 = ((long long)n * c) / 4;
    bn_apply_ff<<<(unsigned)((t4 + 255) / 256), 256, 0, st>>>(X, Y, stats, gb, t4, n, c);
}

static void bn_elu_hh(const __half* X, __half* Y, const float* gb,
                      int n, int c, float* stats, cudaStream_t st)
{
    bn_stats_launch<__half>(X, n, c, stats, st);
    long long t2 = ((long long)n * c) / 2;
    bn_apply_hh<<<(unsigned)((t2 + 255) / 256), 256, 0, st>>>(X, Y, stats, gb, t2, n, c);
}

extern "C" void kernel_launch(void* const* d_in, const int* in_sizes, int n_in,
                              void* d_out, int out_size)
{
    const float* feats0 = (const float*)d_in[0];
    const float* feats1 = (const float*)d_in[1];
    const float* feats2 = (const float*)d_in[2];
    const float* w_out0 = (const float*)d_in[3];
    const float* w_out1 = (const float*)d_in[4];
    const float* w_out2 = (const float*)d_in[5];
    const float* wt2    = (const float*)d_in[6];
    const float* wu2    = (const float*)d_in[7];
    const float* wt1    = (const float*)d_in[8];
    const float* wu1    = (const float*)d_in[9];
    const float* bn_out0 = (const float*)d_in[10];
    const float* bn_out1 = (const float*)d_in[11];
    const float* bn_out2 = (const float*)d_in[12];
    const float* bn_up2a = (const float*)d_in[13];
    const float* bn_up2b = (const float*)d_in[14];
    const float* bn_up1a = (const float*)d_in[15];
    const float* bn_up1b = (const float*)d_in[16];
    const int* m_c2 = (const int*)d_in[19];
    const int* m_g2 = (const int*)d_in[20];
    const int* m_u1 = (const int*)d_in[21];
    const int* m_g1 = (const int*)d_in[22];
    const int* m_u0 = (const int*)d_in[23];
    const int* lat1_idx = (const int*)d_in[24];
    const int* up1_idx  = (const int*)d_in[25];
    const int* lat0_idx = (const int*)d_in[26];
    const int* up0_idx  = (const int*)d_in[27];

    const int N0 = in_sizes[0] / 64;
    const int N1 = in_sizes[1] / 128;
    const int N2 = in_sizes[2] / 256;
    const int U1 = in_sizes[17] / 128;
    const int U0 = in_sizes[18] / 64;
    const int Mc2 = in_sizes[19] / 52;
    const int Mg2 = in_sizes[20] / 52;
    const int Mu1 = in_sizes[21] / 52;
    const int Mg1 = in_sizes[22] / 52;
    const int Mu0 = in_sizes[23] / 52;
    const int G2 = 8 * N2;
    const int G1 = 8 * U1;

    float *acc2, *accg2, *acc1, *accg1, *acc0, *stats;
    __half *f2hbuf, *tg2h, *x1h, *t1h, *x0h, *wh;
    cudaGetSymbolAddress((void**)&acc2,  g_acc2);
    cudaGetSymbolAddress((void**)&accg2, g_accg2);
    cudaGetSymbolAddress((void**)&acc1,  g_acc1);
    cudaGetSymbolAddress((void**)&accg1, g_accg1);
    cudaGetSymbolAddress((void**)&acc0,  g_acc0);
    cudaGetSymbolAddress((void**)&stats, g_stats);
    cudaGetSymbolAddress((void**)&f2hbuf, g_f2h);
    cudaGetSymbolAddress((void**)&tg2h,  g_tg2h);
    cudaGetSymbolAddress((void**)&x1h,   g_x1h);
    cudaGetSymbolAddress((void**)&t1h,   g_t1h);
    cudaGetSymbolAddress((void**)&x0h,   g_x0h);
    cudaGetSymbolAddress((void**)&wh,    g_wh);

    float* out0 = (float*)d_out;
    float* out1 = out0 + (size_t)U0 * 128;
    float* out2 = out1 + (size_t)U1 * 128;

    static cudaStream_t s1 = nullptr;
    static cudaEvent_t eRoot = nullptr, eF2 = nullptr, eX1 = nullptr, eEnd = nullptr;
    if (!s1) {
        cudaStreamCreateWithFlags(&s1, cudaStreamNonBlocking);
        cudaEventCreateWithFlags(&eRoot, cudaEventDisableTiming);
        cudaEventCreateWithFlags(&eF2,   cudaEventDisableTiming);
        cudaEventCreateWithFlags(&eX1,   cudaEventDisableTiming);
        cudaEventCreateWithFlags(&eEnd,  cudaEventDisableTiming);
    }
    cudaStream_t s0 = 0;

    // ---- stream-head memsets (off critical path; overlap weight conversion) ----
    cudaMemsetAsync(stats, 0, 8 * 256 * sizeof(float), s0);
    cudaMemsetAsync(acc2, 0, (size_t)(N2 + 1) * 128 * sizeof(float), s0);
    cudaMemsetAsync(acc1, 0, (size_t)(U1 + 1) * 128 * sizeof(float), s0);

    // ---- fork ----
    cudaEventRecord(eRoot, s0);
    cudaStreamWaitEvent(s1, eRoot, 0);

    cudaMemsetAsync(accg2, 0, (size_t)(G2 + 1) * 128 * sizeof(float), s1);
    cudaMemsetAsync(accg1, 0, (size_t)(G1 + 1) * 64 * sizeof(float), s1);
    cudaMemsetAsync(acc0, 0, (size_t)(U0 + 1) * 128 * sizeof(float), s1);
    cudaMemsetAsync(x1h, 0, (size_t)U1 * 128 * sizeof(__half), s1);
    cudaMemsetAsync(x0h, 0, (size_t)U0 * 64 * sizeof(__half), s1);

    // ===== s0: feats2 fp16 + w_out2, then out2 head =====
    {
        long long t4 = ((long long)N2 * 256) / 4;
        f2h4<<<(unsigned)((t4 + 255) / 256), 256, 0, s0>>>(feats2, f2hbuf, t4);
    }
    cudaEventRecord(eF2, s0);
    wh_launch(w_out2, wh + O_WOUT2, 27, 256, 128, s0);
    sconv3_launch(f2hbuf, wh + O_WOUT2, m_c2, N2, Mc2, 256, 128, acc2, s0);
    bn_elu_ff(acc2, out2, bn_out2, N2, 128, stats + 0*256, s0);
    wh_launch(w_out1, wh + O_WOUT1, 27, 128, 128, s0);

    // ===== s1: weights + union bases + up path =====
    wh_launch(wt2, wh + O_WT2, 8, 256, 128, s1);
    wh_launch(wu2, wh + O_WU2, 27, 128, 128, s1);
    wh_launch(wt1, wh + O_WT1, 8, 128, 64, s1);
    wh_launch(wu1, wh + O_WU1, 27, 64, 64, s1);
    wh_launch(w_out0, wh + O_WOUT0, 27, 64, 128, s1);

    {
        long long t4 = ((long long)N1 * 128) / 4;
        scatter_copy_f2h4<<<(unsigned)((t4 + 255) / 256), 256, 0, s1>>>(feats1, x1h, lat1_idx, t4, 128);
        t4 = ((long long)N0 * 64) / 4;
        scatter_copy_f2h4<<<(unsigned)((t4 + 255) / 256), 256, 0, s1>>>(feats0, x0h, lat0_idx, t4, 64);
    }

    // up block 2 (needs f2hbuf from s0)
    cudaStreamWaitEvent(s1, eF2, 0);
    tconv_launch(f2hbuf, wh + O_WT2, tg2h, N2, 256, 128, s1);
    bn_elu_hh(tg2h, tg2h, bn_up2a, G2, 128, stats + 1*256, s1);
    sconv3_launch(tg2h, wh + O_WU2, m_g2, G2, Mg2, 128, 128, accg2, s1);
    bn_stats_launch<float>(accg2, G2, 128, stats + 2*256, s1);
    {
        long long t2 = ((long long)G2 * 128) / 2;
        bn_apply_add<<<(unsigned)((t2 + 255) / 256), 256, 0, s1>>>(
            accg2, x1h, up1_idx, stats + 2*256, bn_up2b, t2, G2, 128);
    }
    cudaEventRecord(eX1, s1);

    // up block 1
    tconv_launch(x1h, wh + O_WT1, t1h, U1, 128, 64, s1);
    bn_elu_hh(t1h, t1h, bn_up1a, G1, 64, stats + 3*256, s1);
    sconv3_launch(t1h, wh + O_WU1, m_g1, G1, Mg1, 64, 64, accg1, s1);
    bn_stats_launch<float>(accg1, G1, 64, stats + 4*256, s1);
    {
        long long t2 = ((long long)G1 * 64) / 2;
        bn_apply_add<<<(unsigned)((t2 + 255) / 256), 256, 0, s1>>>(
            accg1, x0h, up0_idx, stats + 4*256, bn_up1b, t2, G1, 64);
    }
    // out0 head
    sconv3_launch(x0h, wh + O_WOUT0, m_u0, U0, Mu0, 64, 128, acc0, s1);
    bn_elu_ff(acc0, out0, bn_out0, U0, 128, stats + 5*256, s1);
    cudaEventRecord(eEnd, s1);

    // ===== s0: out1 head, overlapping up-block-1 =====
    cudaStreamWaitEvent(s0, eX1, 0);
    sconv3_launch(x1h, wh + O_WOUT1, m_u1, U1, Mu1, 128, 128, acc1, s0);
    bn_elu_ff(acc1, out1, bn_out1, U1, 128, stats + 6*256, s0);

    // ---- join ----
    cudaStreamWaitEvent(s0, eEnd, 0);
}

// round 14
// speedup vs baseline: 1.0037x; 1.0037x over previous
#include <cuda_runtime.h>
#include <cuda_fp16.h>
#include <math.h>

// ---------------------------------------------------------------------------
// Static scratch (allocation-free per harness rules)
// ---------------------------------------------------------------------------
#define N2MAX 1536
#define G2MAX (8*N2MAX)
#define U1MAX 15872
#define G1MAX (8*U1MAX)
#define U0MAX 160256

__device__ float g_acc2[(N2MAX+1)*128];
__device__ float g_accg2[((size_t)G2MAX+1)*128];
__device__ float g_acc1[((size_t)U1MAX+1)*128];
__device__ float g_accg1[((size_t)G1MAX+1)*64];
__device__ float g_acc0[((size_t)U0MAX+1)*128];
__device__ float g_stats[8*256];

// fp16 GEMM inputs
__device__ __half g_f2h[(size_t)N2MAX*256];
__device__ __half g_tg2h[(size_t)G2MAX*128];
__device__ __half g_x1h[(size_t)U1MAX*128];
__device__ __half g_t1h[(size_t)G1MAX*64];
__device__ __half g_x0h[(size_t)U0MAX*64];
// fp16 weights, n-major [tap][cout][cin]
__device__ __half g_wh[2428928];

#define O_WOUT0 0
#define O_WOUT1 221184
#define O_WOUT2 663552
#define O_WT2   1548288
#define O_WU2   1810432
#define O_WT1   2252800
#define O_WU1   2318336

#define ASTRH 72   // smem row stride in halves (144B): ldsm conflict-free, 16B-aligned

__device__ __forceinline__ unsigned smem_u32(const void* p) {
    unsigned a;
    asm("{ .reg .u64 t; cvta.to.shared.u64 t, %1; cvt.u32.u64 %0, t; }" : "=r"(a) : "l"(p));
    return a;
}
__device__ __forceinline__ void cp_async16z(void* sdst, const void* gsrc, int bytes) {
    unsigned saddr = smem_u32(sdst);
    asm volatile("cp.async.cg.shared.global [%0], [%1], 16, %2;"
                 :: "r"(saddr), "l"(gsrc), "r"(bytes));
}
__device__ __forceinline__ void cp_async16(void* sdst, const void* gsrc) {
    unsigned saddr = smem_u32(sdst);
    asm volatile("cp.async.cg.shared.global [%0], [%1], 16;" :: "r"(saddr), "l"(gsrc));
}
__device__ __forceinline__ void cp_commit_wait() {
    asm volatile("cp.async.commit_group;\n\tcp.async.wait_group 0;" ::: "memory");
}
__device__ __forceinline__ void ldsm_x4(unsigned& r0, unsigned& r1,
                                        unsigned& r2, unsigned& r3, const void* p)
{
    unsigned addr = smem_u32(p);
    asm volatile("ldmatrix.sync.aligned.m8n8.x4.shared.b16 {%0,%1,%2,%3}, [%4];"
                 : "=r"(r0), "=r"(r1), "=r"(r2), "=r"(r3) : "r"(addr));
}
__device__ __forceinline__ void mma_f16(float& c0, float& c1, float& c2, float& c3,
                                        unsigned a0, unsigned a1, unsigned a2, unsigned a3,
                                        unsigned b0, unsigned b1)
{
    asm volatile("mma.sync.aligned.m16n8k16.row.col.f32.f16.f16.f32 "
                 "{%0,%1,%2,%3},{%4,%5,%6,%7},{%8,%9},{%0,%1,%2,%3};"
                 : "+f"(c0), "+f"(c1), "+f"(c2), "+f"(c3)
                 : "r"(a0), "r"(a1), "r"(a2), "r"(a3), "r"(b0), "r"(b1));
}
__device__ __forceinline__ void red_add_v2(float* p, float a, float b) {
    asm volatile("red.global.add.v2.f32 [%0], {%1,%2};"
                 :: "l"(p), "f"(a), "f"(b) : "memory");
}

// ---------------------------------------------------------------------------
// GEMM body: 128 x TN x cin fp16, chunked by 64 k. (unchanged from R12)
// ---------------------------------------------------------------------------
template<int TN>
__device__ __forceinline__ void gemm_body(
    const __half* __restrict__ X, const __half* __restrict__ Wt,
    const int* gidx, __half (*Asm)[ASTRH], __half (*Bsm)[ASTRH],
    int cin, int tid, int wm, int wn, int lane, float (&c)[2][TN/16][4])
{
    constexpr int NI = TN / 16;
    const int ar  = tid >> 1;
    const int as0 = (tid & 1) * 4;
    const int g = gidx[ar];
    const __half* asrc = X + (size_t)(g >= 0 ? g : 0) * cin;
    const int abytes = (g >= 0) ? 16 : 0;
    const int lr = lane & 15;
    const int koff = (lane >> 4) * 8;

    for (int kc = 0; kc < cin; kc += 64) {
        if (kc) __syncthreads();
        #pragma unroll
        for (int j = 0; j < 4; j++) {
            const int seg = as0 + j;
            cp_async16z(&Asm[ar][seg * 8], asrc + kc + seg * 8, abytes);
        }
        #pragma unroll
        for (int l = 0; l < TN / 32; l++) {
            const int idx = tid + l * 256;
            const int nn = idx >> 3, seg = idx & 7;
            cp_async16(&Bsm[nn][seg * 8], Wt + (size_t)nn * cin + kc + seg * 8);
        }
        cp_commit_wait();
        __syncthreads();

        #pragma unroll
        for (int kt = 0; kt < 4; kt++) {
            const int kb = kt * 16 + koff;
            unsigned a[2][4];
            #pragma unroll
            for (int mi = 0; mi < 2; mi++)
                ldsm_x4(a[mi][0], a[mi][1], a[mi][2], a[mi][3],
                        &Asm[wm + mi * 16 + lr][kb]);
            unsigned b[NI][2];
            #pragma unroll
            for (int nj = 0; nj < NI / 2; nj++) {
                unsigned r0, r1, r2, r3;
                ldsm_x4(r0, r1, r2, r3, &Bsm[wn + nj * 16 + lr][kb]);
                b[2*nj][0] = r0; b[2*nj+1][0] = r1;
                b[2*nj][1] = r2; b[2*nj+1][1] = r3;
            }
            #pragma unroll
            for (int mi = 0; mi < 2; mi++)
                #pragma unroll
                for (int ni = 0; ni < NI; ni++)
                    mma_f16(c[mi][ni][0], c[mi][ni][1], c[mi][ni][2], c[mi][ni][3],
                            a[mi][0], a[mi][1], a[mi][2], a[mi][3], b[ni][0], b[ni][1]);
        }
    }
}

// ---------------------------------------------------------------------------
// Scatter-style tap conv (fp16 HMMA + fp32 RED). grid = (ceil(n/128), 27)
// ---------------------------------------------------------------------------
template<int TN, int MAXCTA>
__global__ __launch_bounds__(256, MAXCTA) void conv3(
    const __half* __restrict__ X, const __half* __restrict__ W27,
    float* __restrict__ C, const int* __restrict__ maps,
    int Mpad, int n, int cin)
{
    constexpr int NI = TN / 16;
    __shared__ __align__(16) __half Asm[128][ASTRH];
    __shared__ __align__(16) __half Bsm[TN][ASTRH];
    __shared__ int gidx[128], sidx[128];

    const int z    = blockIdx.y;
    const int Mz   = (z == 26) ? n : Mpad;
    const int row0 = blockIdx.x * 128;
    if (row0 >= Mz) return;

    const int tap  = (z == 26) ? 13 : ((z < 13) ? z : z + 1);
    const __half* Wt = W27 + (size_t)tap * cin * TN;
    const int tid  = threadIdx.x;
    const int scrap = n;

    int myvalid = 0;
    if (tid < 128) {
        int r = row0 + tid;
        int g = -1, s = -1;
        if (r < Mz) {
            if (z == 26) { g = r; s = r; }
            else {
                g = maps[(size_t)z * Mpad + r];
                s = maps[(size_t)(26 + z) * Mpad + r];
            }
        }
        gidx[tid] = g;
        sidx[tid] = s;
        myvalid = (s >= 0 && s != scrap);
    }
    if (__syncthreads_count(myvalid) == 0) return;

    const int lane = tid & 31;
    const int warp = tid >> 5;
    const int wm = (warp & 3) * 32;
    const int wn = (warp >> 2) * (TN / 2);

    float c[2][NI][4];
    #pragma unroll
    for (int mi = 0; mi < 2; mi++)
        #pragma unroll
        for (int ni = 0; ni < NI; ni++)
            #pragma unroll
            for (int j = 0; j < 4; j++) c[mi][ni][j] = 0.f;

    gemm_body<TN>(X, Wt, gidx, Asm, Bsm, cin, tid, wm, wn, lane, c);

    const int qr = lane >> 2, qc = lane & 3;
    #pragma unroll
    for (int mi = 0; mi < 2; mi++) {
        #pragma unroll
        for (int half_ = 0; half_ < 2; half_++) {
            const int lr2 = wm + mi * 16 + qr + half_ * 8;
            const int o = sidx[lr2];
            if (o < 0 || o == scrap) continue;
            float* cp = C + (size_t)o * TN + wn + qc * 2;
            #pragma unroll
            for (int ni = 0; ni < NI; ni++)
                red_add_v2(cp + ni * 8, c[mi][ni][half_*2], c[mi][ni][half_*2+1]);
        }
    }
}

// ---------------------------------------------------------------------------
// Batched transpose conv (fp16 in, fp16 out): T[z*n + r] = X[r] @ Wt[z]
// ---------------------------------------------------------------------------
template<int TN, int MAXCTA>
__global__ __launch_bounds__(256, MAXCTA) void tconv3(
    const __half* __restrict__ X, const __half* __restrict__ W8,
    __half* __restrict__ T, int n, int cin)
{
    constexpr int NI = TN / 16;
    __shared__ __align__(16) __half Asm[128][ASTRH];
    __shared__ __align__(16) __half Bsm[TN][ASTRH];
    __shared__ int gidx[128];

    const int z    = blockIdx.y;
    const int row0 = blockIdx.x * 128;
    if (row0 >= n) return;
    const __half* Wt = W8 + (size_t)z * cin * TN;
    const int tid  = threadIdx.x;

    if (tid < 128) {
        int r = row0 + tid;
        gidx[tid] = (r < n) ? r : -1;
    }
    __syncthreads();

    const int lane = tid & 31;
    const int warp = tid >> 5;
    const int wm = (warp & 3) * 32;
    const int wn = (warp >> 2) * (TN / 2);

    float c[2][NI][4];
    #pragma unroll
    for (int mi = 0; mi < 2; mi++)
        #pragma unroll
        for (int ni = 0; ni < NI; ni++)
            #pragma unroll
            for (int j = 0; j < 4; j++) c[mi][ni][j] = 0.f;

    gemm_body<TN>(X, Wt, gidx, Asm, Bsm, cin, tid, wm, wn, lane, c);

    const int qr = lane >> 2, qc = lane & 3;
    #pragma unroll
    for (int mi = 0; mi < 2; mi++) {
        #pragma unroll
        for (int half_ = 0; half_ < 2; half_++) {
            const int r = row0 + wm + mi * 16 + qr + half_ * 8;
            if (r >= n) continue;
            __half* tp = T + ((size_t)z * n + r) * TN + wn + qc * 2;
            #pragma unroll
            for (int ni = 0; ni < NI; ni++) {
                __half2 hv = __floats2half2_rn(c[mi][ni][half_*2], c[mi][ni][half_*2+1]);
                *reinterpret_cast<__half2*>(tp + ni * 8) = hv;
            }
        }
    }
}

// ---------------------------------------------------------------------------
// One-shot converters (vectorized)
// ---------------------------------------------------------------------------
__global__ void build_wh(const float* __restrict__ src, __half* __restrict__ dst,
                         long long total, int cin, int cout)
{
    long long i = (long long)blockIdx.x * blockDim.x + threadIdx.x;
    if (i >= total) return;
    const long long per = (long long)cin * cout;
    const int t = (int)(i / per);
    const int rem = (int)(i % per);
    const int k = rem / cout, nn = rem % cout;
    dst[(long long)t * per + (long long)nn * cin + k] = __float2half(src[i]);
}

__global__ void f2h4(const float* __restrict__ src, __half* __restrict__ dst, long long n4)
{
    long long i = (long long)blockIdx.x * blockDim.x + threadIdx.x;
    if (i >= n4) return;
    float4 v = ((const float4*)src)[i];
    __half2 h0 = __floats2half2_rn(v.x, v.y);
    __half2 h1 = __floats2half2_rn(v.z, v.w);
    ((uint2*)dst)[i] = make_uint2(*(unsigned*)&h0, *(unsigned*)&h1);
}

// ---------------------------------------------------------------------------
// BatchNorm (training-mode batch stats) + ELU -- vectorized
// ---------------------------------------------------------------------------
template<typename T>
__global__ void bn_stats(const T* __restrict__ X, int n, int c, int rpb,
                         float* __restrict__ stats)
{
    const int c2 = c >> 1;
    const int tpr = blockDim.x / c2;
    const int ch2 = threadIdx.x % c2;
    const int rg = threadIdx.x / c2;
    const int r0 = blockIdx.x * rpb;
    int rend = r0 + rpb; if (rend > n) rend = n;
    float s0 = 0.f, sq0 = 0.f, s1 = 0.f, sq1 = 0.f;
    for (int r = r0 + rg; r < rend; r += tpr) {
        float v0, v1;
        if (sizeof(T) == 2) {
            __half2 h = *(const __half2*)((const __half*)X + (size_t)r * c + ch2 * 2);
            v0 = __low2float(h); v1 = __high2float(h);
        } else {
            float2 f = *(const float2*)((const float*)X + (size_t)r * c + ch2 * 2);
            v0 = f.x; v1 = f.y;
        }
        s0 += v0; sq0 += v0 * v0;
        s1 += v1; sq1 += v1 * v1;
    }
    atomicAdd(&stats[ch2*2],       s0);
    atomicAdd(&stats[ch2*2+1],     s1);
    atomicAdd(&stats[c + ch2*2],   sq0);
    atomicAdd(&stats[c + ch2*2+1], sq1);
}

// final output: fp32 acc -> fp32 out (float4)
__global__ void bn_apply_ff(const float* __restrict__ X, float* __restrict__ Y,
                            const float* __restrict__ stats,
                            const float* __restrict__ gb, long long total4, int n, int c)
{
    long long i = (long long)blockIdx.x * blockDim.x + threadIdx.x;
    if (i >= total4) return;
    const float inv_n = 1.f / (float)n;
    const int ch0 = (int)((i * 4) % c);
    float4 x = ((const float4*)X)[i];
    float4 y;
    #pragma unroll
    for (int j = 0; j < 4; j++) {
        const int ch = ch0 + j;
        float mu  = stats[ch] * inv_n;
        float var = stats[c + ch] * inv_n - mu * mu;
        float xv = (&x.x)[j];
        float v = gb[ch] * (xv - mu) * rsqrtf(var + 1e-5f) + gb[c + ch];
        (&y.x)[j] = (v > 0.f) ? v : expm1f(v);
    }
    ((float4*)Y)[i] = y;
}

// intermediate: fp16 in-place (half2)
__global__ void bn_apply_hh(const __half* __restrict__ X, __half* __restrict__ Y,
                            const float* __restrict__ stats,
                            const float* __restrict__ gb, long long total2, int n, int c)
{
    long long i = (long long)blockIdx.x * blockDim.x + threadIdx.x;
    if (i >= total2) return;
    const float inv_n = 1.f / (float)n;
    const int ch0 = (int)((i * 2) % c);
    __half2 h = ((const __half2*)X)[i];
    float xv0 = __low2float(h), xv1 = __high2float(h);
    float mu0  = stats[ch0] * inv_n;
    float var0 = stats[c + ch0] * inv_n - mu0 * mu0;
    float v0 = gb[ch0] * (xv0 - mu0) * rsqrtf(var0 + 1e-5f) + gb[c + ch0];
    v0 = (v0 > 0.f) ? v0 : expm1f(v0);
    float mu1  = stats[ch0+1] * inv_n;
    float var1 = stats[c + ch0+1] * inv_n - mu1 * mu1;
    float v1 = gb[ch0+1] * (xv1 - mu1) * rsqrtf(var1 + 1e-5f) + gb[c + ch0+1];
    v1 = (v1 > 0.f) ? v1 : expm1f(v1);
    ((__half2*)Y)[i] = __floats2half2_rn(v0, v1);
}

// fused: DSTh[idx[r]] += elu(bn(ACC[r]))  (half2)
__global__ void bn_apply_add(const float* __restrict__ ACC, __half* __restrict__ DST,
                             const int* __restrict__ idx,
                             const float* __restrict__ stats,
                             const float* __restrict__ gb, long long total2, int n, int c)
{
    long long i = (long long)blockIdx.x * blockDim.x + threadIdx.x;
    if (i >= total2) return;
    const float inv_n = 1.f / (float)n;
    const long long e = i * 2;
    const int r = (int)(e / c), ch0 = (int)(e % c);
    float2 x = ((const float2*)ACC)[i];
    float mu0  = stats[ch0] * inv_n;
    float var0 = stats[c + ch0] * inv_n - mu0 * mu0;
    float v0 = gb[ch0] * (x.x - mu0) * rsqrtf(var0 + 1e-5f) + gb[c + ch0];
    v0 = (v0 > 0.f) ? v0 : expm1f(v0);
    float mu1  = stats[ch0+1] * inv_n;
    float var1 = stats[c + ch0+1] * inv_n - mu1 * mu1;
    float v1 = gb[ch0+1] * (x.y - mu1) * rsqrtf(var1 + 1e-5f) + gb[c + ch0+1];
    v1 = (v1 > 0.f) ? v1 : expm1f(v1);
    __half2* p = (__half2*)(DST + (size_t)idx[r] * c + ch0);
    __half2 old = *p;
    *p = __floats2half2_rn(__low2float(old) + v0, __high2float(old) + v1);
}

// scatter: dsth[idx[r]] = f2h(src[r])  (4 elems)
__global__ void scatter_copy_f2h4(const float* __restrict__ src, __half* __restrict__ dst,
                                  const int* __restrict__ idx, long long total4, int c)
{
    long long i = (long long)blockIdx.x * blockDim.x + threadIdx.x;
    if (i >= total4) return;
    const long long e = i * 4;
    const int r = (int)(e / c), ch = (int)(e % c);
    float4 v = ((const float4*)src)[i];
    __half2 h0 = __floats2half2_rn(v.x, v.y);
    __half2 h1 = __floats2half2_rn(v.z, v.w);
    *(uint2*)(dst + (size_t)idx[r] * c + ch) = make_uint2(*(unsigned*)&h0, *(unsigned*)&h1);
}

// ---------------------------------------------------------------------------
// Host-side orchestration (R12 structure: memsets inline per conv)
// ---------------------------------------------------------------------------
static void wh_launch(const float* src, __half* dst, int taps, int cin, int cout,
                      cudaStream_t st)
{
    long long total = (long long)taps * cin * cout;
    build_wh<<<(unsigned)((total + 255) / 256), 256, 0, st>>>(src, dst, total, cin, cout);
}

static void sconv3_launch(const __half* X, const __half* W27, const int* m,
                          int n, int Mpad, int cin, int cout, float* acc,
                          cudaStream_t st)
{
    cudaMemsetAsync(acc, 0, (size_t)(n + 1) * cout * sizeof(float), st);
    dim3 grid((n + 127) / 128, 27);
    if (cout == 128)
        conv3<128, 2><<<grid, 256, 0, st>>>(X, W27, acc, m, Mpad, n, cin);
    else
        conv3<64, 3><<<grid, 256, 0, st>>>(X, W27, acc, m, Mpad, n, cin);
}

static void tconv_launch(const __half* X, const __half* W8, __half* T,
                         int n, int cin, int cout, cudaStream_t st)
{
    dim3 grid((n + 127) / 128, 8);
    if (cout == 128)
        tconv3<128, 2><<<grid, 256, 0, st>>>(X, W8, T, n, cin);
    else
        tconv3<64, 3><<<grid, 256, 0, st>>>(X, W8, T, n, cin);
}

template<typename T>
static void bn_stats_launch(const T* X, int n, int c, float* stats, cudaStream_t st)
{
    const int rpb = (n >= 16384) ? 128 : 32;
    const int c2 = c / 2;
    bn_stats<T><<<(n + rpb - 1) / rpb, c2 * (256 / c2), 0, st>>>(X, n, c, rpb, stats);
}

static void bn_elu_ff(const float* X, float* Y, const float* gb,
                      int n, int c, float* stats, cudaStream_t st)
{
    bn_stats_launch<float>(X, n, c, stats, st);
    long long t4 = ((long long)n * c) / 4;
    bn_apply_ff<<<(unsigned)((t4 + 255) / 256), 256, 0, st>>>(X, Y, stats, gb, t4, n, c);
}

static void bn_elu_hh(const __half* X, __half* Y, const float* gb,
                      int n, int c, float* stats, cudaStream_t st)
{
    bn_stats_launch<__half>(X, n, c, stats, st);
    long long t2 = ((long long)n * c) / 2;
    bn_apply_hh<<<(unsigned)((t2 + 255) / 256), 256, 0, st>>>(X, Y, stats, gb, t2, n, c);
}

extern "C" void kernel_launch(void* const* d_in, const int* in_sizes, int n_in,
                              void* d_out, int out_size)
{
    const float* feats0 = (const float*)d_in[0];
    const float* feats1 = (const float*)d_in[1];
    const float* feats2 = (const float*)d_in[2];
    const float* w_out0 = (const float*)d_in[3];
    const float* w_out1 = (const float*)d_in[4];
    const float* w_out2 = (const float*)d_in[5];
    const float* wt2    = (const float*)d_in[6];
    const float* wu2    = (const float*)d_in[7];
    const float* wt1    = (const float*)d_in[8];
    const float* wu1    = (const float*)d_in[9];
    const float* bn_out0 = (const float*)d_in[10];
    const float* bn_out1 = (const float*)d_in[11];
    const float* bn_out2 = (const float*)d_in[12];
    const float* bn_up2a = (const float*)d_in[13];
    const float* bn_up2b = (const float*)d_in[14];
    const float* bn_up1a = (const float*)d_in[15];
    const float* bn_up1b = (const float*)d_in[16];
    const int* m_c2 = (const int*)d_in[19];
    const int* m_g2 = (const int*)d_in[20];
    const int* m_u1 = (const int*)d_in[21];
    const int* m_g1 = (const int*)d_in[22];
    const int* m_u0 = (const int*)d_in[23];
    const int* lat1_idx = (const int*)d_in[24];
    const int* up1_idx  = (const int*)d_in[25];
    const int* lat0_idx = (const int*)d_in[26];
    const int* up0_idx  = (const int*)d_in[27];

    const int N0 = in_sizes[0] / 64;
    const int N1 = in_sizes[1] / 128;
    const int N2 = in_sizes[2] / 256;
    const int U1 = in_sizes[17] / 128;
    const int U0 = in_sizes[18] / 64;
    const int Mc2 = in_sizes[19] / 52;
    const int Mg2 = in_sizes[20] / 52;
    const int Mu1 = in_sizes[21] / 52;
    const int Mg1 = in_sizes[22] / 52;
    const int Mu0 = in_sizes[23] / 52;
    const int G2 = 8 * N2;
    const int G1 = 8 * U1;

    float *acc2, *accg2, *acc1, *accg1, *acc0, *stats;
    __half *f2hbuf, *tg2h, *x1h, *t1h, *x0h, *wh;
    cudaGetSymbolAddress((void**)&acc2,  g_acc2);
    cudaGetSymbolAddress((void**)&accg2, g_accg2);
    cudaGetSymbolAddress((void**)&acc1,  g_acc1);
    cudaGetSymbolAddress((void**)&accg1, g_accg1);
    cudaGetSymbolAddress((void**)&acc0,  g_acc0);
    cudaGetSymbolAddress((void**)&stats, g_stats);
    cudaGetSymbolAddress((void**)&f2hbuf, g_f2h);
    cudaGetSymbolAddress((void**)&tg2h,  g_tg2h);
    cudaGetSymbolAddress((void**)&x1h,   g_x1h);
    cudaGetSymbolAddress((void**)&t1h,   g_t1h);
    cudaGetSymbolAddress((void**)&x0h,   g_x0h);
    cudaGetSymbolAddress((void**)&wh,    g_wh);

    float* out0 = (float*)d_out;
    float* out1 = out0 + (size_t)U0 * 128;
    float* out2 = out1 + (size_t)U1 * 128;

    static cudaStream_t s1 = nullptr;
    static cudaEvent_t eRoot = nullptr, eF2 = nullptr, eX1 = nullptr, eEnd = nullptr;
    if (!s1) {
        cudaStreamCreateWithFlags(&s1, cudaStreamNonBlocking);
        cudaEventCreateWithFlags(&eRoot, cudaEventDisableTiming);
        cudaEventCreateWithFlags(&eF2,   cudaEventDisableTiming);
        cudaEventCreateWithFlags(&eX1,   cudaEventDisableTiming);
        cudaEventCreateWithFlags(&eEnd,  cudaEventDisableTiming);
    }
    cudaStream_t s0 = 0;

    // zero all bn-stats slots once
    cudaMemsetAsync(stats, 0, 8 * 256 * sizeof(float), s0);

    // ---- fork ----
    cudaEventRecord(eRoot, s0);
    cudaStreamWaitEvent(s1, eRoot, 0);

    // ===== s0: feats2 fp16 + w_out2, then out2 head =====
    {
        long long t4 = ((long long)N2 * 256) / 4;
        f2h4<<<(unsigned)((t4 + 255) / 256), 256, 0, s0>>>(feats2, f2hbuf, t4);
    }
    cudaEventRecord(eF2, s0);
    wh_launch(w_out2, wh + O_WOUT2, 27, 256, 128, s0);
    sconv3_launch(f2hbuf, wh + O_WOUT2, m_c2, N2, Mc2, 256, 128, acc2, s0);
    bn_elu_ff(acc2, out2, bn_out2, N2, 128, stats + 0*256, s0);
    wh_launch(w_out1, wh + O_WOUT1, 27, 128, 128, s0);

    // ===== s1: weights + union bases + up path =====
    wh_launch(wt2, wh + O_WT2, 8, 256, 128, s1);
    wh_launch(wu2, wh + O_WU2, 27, 128, 128, s1);
    wh_launch(wt1, wh + O_WT1, 8, 128, 64, s1);
    wh_launch(wu1, wh + O_WU1, 27, 64, 64, s1);
    wh_launch(w_out0, wh + O_WOUT0, 27, 64, 128, s1);

    cudaMemsetAsync(x1h, 0, (size_t)U1 * 128 * sizeof(__half), s1);
    {
        long long t4 = ((long long)N1 * 128) / 4;
        scatter_copy_f2h4<<<(unsigned)((t4 + 255) / 256), 256, 0, s1>>>(feats1, x1h, lat1_idx, t4, 128);
    }
    cudaMemsetAsync(x0h, 0, (size_t)U0 * 64 * sizeof(__half), s1);
    {
        long long t4 = ((long long)N0 * 64) / 4;
        scatter_copy_f2h4<<<(unsigned)((t4 + 255) / 256), 256, 0, s1>>>(feats0, x0h, lat0_idx, t4, 64);
    }

    // up block 2 (needs f2hbuf from s0)
    cudaStreamWaitEvent(s1, eF2, 0);
    tconv_launch(f2hbuf, wh + O_WT2, tg2h, N2, 256, 128, s1);
    bn_elu_hh(tg2h, tg2h, bn_up2a, G2, 128, stats + 1*256, s1);
    sconv3_launch(tg2h, wh + O_WU2, m_g2, G2, Mg2, 128, 128, accg2, s1);
    bn_stats_launch<float>(accg2, G2, 128, stats + 2*256, s1);
    {
        long long t2 = ((long long)G2 * 128) / 2;
        bn_apply_add<<<(unsigned)((t2 + 255) / 256), 256, 0, s1>>>(
            accg2, x1h, up1_idx, stats + 2*256, bn_up2b, t2, G2, 128);
    }
    cudaEventRecord(eX1, s1);

    // up block 1
    tconv_launch(x1h, wh + O_WT1, t1h, U1, 128, 64, s1);
    bn_elu_hh(t1h, t1h, bn_up1a, G1, 64, stats + 3*256, s1);
    sconv3_launch(t1h, wh + O_WU1, m_g1, G1, Mg1, 64, 64, accg1, s1);
    bn_stats_launch<float>(accg1, G1, 64, stats + 4*256, s1);
    {
        long long t2 = ((long long)G1 * 64) / 2;
        bn_apply_add<<<(unsigned)((t2 + 255) / 256), 256, 0, s1>>>(
            accg1, x0h, up0_idx, stats + 4*256, bn_up1b, t2, G1, 64);
    }
    // out0 head
    sconv3_launch(x0h, wh + O_WOUT0, m_u0, U0, Mu0, 64, 128, acc0, s1);
    bn_elu_ff(acc0, out0, bn_out0, U0, 128, stats + 5*256, s1);
    cudaEventRecord(eEnd, s1);

    // ===== s0: out1 head, overlapping up-block-1 =====
    cudaStreamWaitEvent(s0, eX1, 0);
    sconv3_launch(x1h, wh + O_WOUT1, m_u1, U1, Mu1, 128, 128, acc1, s0);
    bn_elu_ff(acc1, out1, bn_out1, U1, 128, stats + 6*256, s0);

    // ---- join ----
    cudaStreamWaitEvent(s0, eEnd, 0);
}

// round 15
// speedup vs baseline: 1.1439x; 1.1397x over previous
#include <cuda_runtime.h>
#include <cuda_fp16.h>
#include <math.h>

// ---------------------------------------------------------------------------
// Static scratch (allocation-free per harness rules)
// ---------------------------------------------------------------------------
#define N2MAX 1536
#define G2MAX (8*N2MAX)
#define U1MAX 15872
#define G1MAX (8*U1MAX)
#define U0MAX 160256

__device__ float g_acc2[(N2MAX+1)*128];
__device__ float g_accg2[((size_t)G2MAX+1)*128];
__device__ float g_acc1[((size_t)U1MAX+1)*128];
__device__ float g_accg1[((size_t)G1MAX+1)*64];
__device__ float g_acc0[((size_t)U0MAX+1)*128];
__device__ float g_stats[8*256];

// fp16 GEMM inputs
__device__ __half g_f2h[(size_t)N2MAX*256];
__device__ __half g_tg2h[(size_t)G2MAX*128];
__device__ __half g_x1h[(size_t)U1MAX*128];
__device__ __half g_t1h[(size_t)G1MAX*64];
__device__ __half g_x0h[(size_t)U0MAX*64];
// fp16 weights, n-major [tap][cout][cin]
__device__ __half g_wh[2428928];

#define O_WOUT0 0
#define O_WOUT1 221184
#define O_WOUT2 663552
#define O_WT2   1548288
#define O_WU2   1810432
#define O_WT1   2252800
#define O_WU1   2318336

#define ASTRH 72   // smem row stride in halves (144B): ldsm conflict-free, 16B-aligned

__device__ __forceinline__ unsigned smem_u32(const void* p) {
    unsigned a;
    asm("{ .reg .u64 t; cvta.to.shared.u64 t, %1; cvt.u32.u64 %0, t; }" : "=r"(a) : "l"(p));
    return a;
}
__device__ __forceinline__ void cp_async16z(void* sdst, const void* gsrc, int bytes) {
    unsigned saddr = smem_u32(sdst);
    asm volatile("cp.async.cg.shared.global [%0], [%1], 16, %2;"
                 :: "r"(saddr), "l"(gsrc), "r"(bytes));
}
__device__ __forceinline__ void cp_async16(void* sdst, const void* gsrc) {
    unsigned saddr = smem_u32(sdst);
    asm volatile("cp.async.cg.shared.global [%0], [%1], 16;" :: "r"(saddr), "l"(gsrc));
}
__device__ __forceinline__ void cp_commit_wait() {
    asm volatile("cp.async.commit_group;\n\tcp.async.wait_group 0;" ::: "memory");
}
__device__ __forceinline__ void ldsm_x4(unsigned& r0, unsigned& r1,
                                        unsigned& r2, unsigned& r3, const void* p)
{
    unsigned addr = smem_u32(p);
    asm volatile("ldmatrix.sync.aligned.m8n8.x4.shared.b16 {%0,%1,%2,%3}, [%4];"
                 : "=r"(r0), "=r"(r1), "=r"(r2), "=r"(r3) : "r"(addr));
}
__device__ __forceinline__ void mma_f16(float& c0, float& c1, float& c2, float& c3,
                                        unsigned a0, unsigned a1, unsigned a2, unsigned a3,
                                        unsigned b0, unsigned b1)
{
    asm volatile("mma.sync.aligned.m16n8k16.row.col.f32.f16.f16.f32 "
                 "{%0,%1,%2,%3},{%4,%5,%6,%7},{%8,%9},{%0,%1,%2,%3};"
                 : "+f"(c0), "+f"(c1), "+f"(c2), "+f"(c3)
                 : "r"(a0), "r"(a1), "r"(a2), "r"(a3), "r"(b0), "r"(b1));
}
__device__ __forceinline__ void red_add_v2(float* p, float a, float b) {
    asm volatile("red.global.add.v2.f32 [%0], {%1,%2};"
                 :: "l"(p), "f"(a), "f"(b) : "memory");
}

// ---------------------------------------------------------------------------
// GEMM body: 128 x TN x cin fp16, chunked by 64 k. (exact R12)
// ---------------------------------------------------------------------------
template<int TN>
__device__ __forceinline__ void gemm_body(
    const __half* __restrict__ X, const __half* __restrict__ Wt,
    const int* gidx, __half (*Asm)[ASTRH], __half (*Bsm)[ASTRH],
    int cin, int tid, int wm, int wn, int lane, float (&c)[2][TN/16][4])
{
    constexpr int NI = TN / 16;
    const int ar  = tid >> 1;
    const int as0 = (tid & 1) * 4;
    const int g = gidx[ar];
    const __half* asrc = X + (size_t)(g >= 0 ? g : 0) * cin;
    const int abytes = (g >= 0) ? 16 : 0;
    const int lr = lane & 15;
    const int koff = (lane >> 4) * 8;

    for (int kc = 0; kc < cin; kc += 64) {
        if (kc) __syncthreads();
        #pragma unroll
        for (int j = 0; j < 4; j++) {
            const int seg = as0 + j;
            cp_async16z(&Asm[ar][seg * 8], asrc + kc + seg * 8, abytes);
        }
        #pragma unroll
        for (int l = 0; l < TN / 32; l++) {
            const int idx = tid + l * 256;
            const int nn = idx >> 3, seg = idx & 7;
            cp_async16(&Bsm[nn][seg * 8], Wt + (size_t)nn * cin + kc + seg * 8);
        }
        cp_commit_wait();
        __syncthreads();

        #pragma unroll
        for (int kt = 0; kt < 4; kt++) {
            const int kb = kt * 16 + koff;
            unsigned a[2][4];
            #pragma unroll
            for (int mi = 0; mi < 2; mi++)
                ldsm_x4(a[mi][0], a[mi][1], a[mi][2], a[mi][3],
                        &Asm[wm + mi * 16 + lr][kb]);
            unsigned b[NI][2];
            #pragma unroll
            for (int nj = 0; nj < NI / 2; nj++) {
                unsigned r0, r1, r2, r3;
                ldsm_x4(r0, r1, r2, r3, &Bsm[wn + nj * 16 + lr][kb]);
                b[2*nj][0] = r0; b[2*nj+1][0] = r1;
                b[2*nj][1] = r2; b[2*nj+1][1] = r3;
            }
            #pragma unroll
            for (int mi = 0; mi < 2; mi++)
                #pragma unroll
                for (int ni = 0; ni < NI; ni++)
                    mma_f16(c[mi][ni][0], c[mi][ni][1], c[mi][ni][2], c[mi][ni][3],
                            a[mi][0], a[mi][1], a[mi][2], a[mi][3], b[ni][0], b[ni][1]);
        }
    }
}

// ---------------------------------------------------------------------------
// Scatter-style tap conv (fp16 HMMA + fp32 RED). grid = (ceil(n/128), 27)
// ---------------------------------------------------------------------------
template<int TN, int MAXCTA>
__global__ __launch_bounds__(256, MAXCTA) void conv3(
    const __half* __restrict__ X, const __half* __restrict__ W27,
    float* __restrict__ C, const int* __restrict__ maps,
    int Mpad, int n, int cin)
{
    constexpr int NI = TN / 16;
    __shared__ __align__(16) __half Asm[128][ASTRH];
    __shared__ __align__(16) __half Bsm[TN][ASTRH];
    __shared__ int gidx[128], sidx[128];

    const int z    = blockIdx.y;
    const int Mz   = (z == 26) ? n : Mpad;
    const int row0 = blockIdx.x * 128;
    if (row0 >= Mz) return;

    const int tap  = (z == 26) ? 13 : ((z < 13) ? z : z + 1);
    const __half* Wt = W27 + (size_t)tap * cin * TN;
    const int tid  = threadIdx.x;
    const int scrap = n;

    int myvalid = 0;
    if (tid < 128) {
        int r = row0 + tid;
        int g = -1, s = -1;
        if (r < Mz) {
            if (z == 26) { g = r; s = r; }
            else {
                g = maps[(size_t)z * Mpad + r];
                s = maps[(size_t)(26 + z) * Mpad + r];
            }
        }
        gidx[tid] = g;
        sidx[tid] = s;
        myvalid = (s >= 0 && s != scrap);
    }
    if (__syncthreads_count(myvalid) == 0) return;

    const int lane = tid & 31;
    const int warp = tid >> 5;
    const int wm = (warp & 3) * 32;
    const int wn = (warp >> 2) * (TN / 2);

    float c[2][NI][4];
    #pragma unroll
    for (int mi = 0; mi < 2; mi++)
        #pragma unroll
        for (int ni = 0; ni < NI; ni++)
            #pragma unroll
            for (int j = 0; j < 4; j++) c[mi][ni][j] = 0.f;

    gemm_body<TN>(X, Wt, gidx, Asm, Bsm, cin, tid, wm, wn, lane, c);

    const int qr = lane >> 2, qc = lane & 3;
    #pragma unroll
    for (int mi = 0; mi < 2; mi++) {
        #pragma unroll
        for (int half_ = 0; half_ < 2; half_++) {
            const int lr2 = wm + mi * 16 + qr + half_ * 8;
            const int o = sidx[lr2];
            if (o < 0 || o == scrap) continue;
            float* cp = C + (size_t)o * TN + wn + qc * 2;
            #pragma unroll
            for (int ni = 0; ni < NI; ni++)
                red_add_v2(cp + ni * 8, c[mi][ni][half_*2], c[mi][ni][half_*2+1]);
        }
    }
}

// ---------------------------------------------------------------------------
// Batched transpose conv (fp16 in, fp16 out): T[z*n + r] = X[r] @ Wt[z]
// ---------------------------------------------------------------------------
template<int TN, int MAXCTA>
__global__ __launch_bounds__(256, MAXCTA) void tconv3(
    const __half* __restrict__ X, const __half* __restrict__ W8,
    __half* __restrict__ T, int n, int cin)
{
    constexpr int NI = TN / 16;
    __shared__ __align__(16) __half Asm[128][ASTRH];
    __shared__ __align__(16) __half Bsm[TN][ASTRH];
    __shared__ int gidx[128];

    const int z    = blockIdx.y;
    const int row0 = blockIdx.x * 128;
    if (row0 >= n) return;
    const __half* Wt = W8 + (size_t)z * cin * TN;
    const int tid  = threadIdx.x;

    if (tid < 128) {
        int r = row0 + tid;
        gidx[tid] = (r < n) ? r : -1;
    }
    __syncthreads();

    const int lane = tid & 31;
    const int warp = tid >> 5;
    const int wm = (warp & 3) * 32;
    const int wn = (warp >> 2) * (TN / 2);

    float c[2][NI][4];
    #pragma unroll
    for (int mi = 0; mi < 2; mi++)
        #pragma unroll
        for (int ni = 0; ni < NI; ni++)
            #pragma unroll
            for (int j = 0; j < 4; j++) c[mi][ni][j] = 0.f;

    gemm_body<TN>(X, Wt, gidx, Asm, Bsm, cin, tid, wm, wn, lane, c);

    const int qr = lane >> 2, qc = lane & 3;
    #pragma unroll
    for (int mi = 0; mi < 2; mi++) {
        #pragma unroll
        for (int half_ = 0; half_ < 2; half_++) {
            const int r = row0 + wm + mi * 16 + qr + half_ * 8;
            if (r >= n) continue;
            __half* tp = T + ((size_t)z * n + r) * TN + wn + qc * 2;
            #pragma unroll
            for (int ni = 0; ni < NI; ni++) {
                __half2 hv = __floats2half2_rn(c[mi][ni][half_*2], c[mi][ni][half_*2+1]);
                *reinterpret_cast<__half2*>(tp + ni * 8) = hv;
            }
        }
    }
}

// ---------------------------------------------------------------------------
// One-shot converters (exact R12 scalar versions)
// ---------------------------------------------------------------------------
__global__ void build_wh(const float* __restrict__ src, __half* __restrict__ dst,
                         long long total, int cin, int cout)
{
    long long i = (long long)blockIdx.x * blockDim.x + threadIdx.x;
    if (i >= total) return;
    const long long per = (long long)cin * cout;
    const int t = (int)(i / per);
    const int rem = (int)(i % per);
    const int k = rem / cout, nn = rem % cout;
    dst[(long long)t * per + (long long)nn * cin + k] = __float2half(src[i]);
}

__global__ void f2h(const float* __restrict__ src, __half* __restrict__ dst, long long n)
{
    long long i = (long long)blockIdx.x * blockDim.x + threadIdx.x;
    if (i >= n) return;
    dst[i] = __float2half(src[i]);
}

// ---------------------------------------------------------------------------
// BatchNorm (training-mode batch stats) + ELU (exact R12 scalar versions)
// ---------------------------------------------------------------------------
template<typename T>
__global__ void bn_stats(const T* __restrict__ X, int n, int c, int rpb,
                         float* __restrict__ stats)
{
    const int tpr = blockDim.x / c;
    const int ch = threadIdx.x % c;
    const int rg = threadIdx.x / c;
    const int r0 = blockIdx.x * rpb;
    int rend = r0 + rpb; if (rend > n) rend = n;
    float s = 0.f, sq = 0.f;
    for (int r = r0 + rg; r < rend; r += tpr) {
        float v = (float)X[(size_t)r * c + ch];
        s += v; sq += v * v;
    }
    atomicAdd(&stats[ch], s);
    atomicAdd(&stats[c + ch], sq);
}

__global__ void bn_apply_ff(const float* __restrict__ X, float* __restrict__ Y,
                            const float* __restrict__ stats,
                            const float* __restrict__ gb, long long total, int n, int c)
{
    long long i = (long long)blockIdx.x * blockDim.x + threadIdx.x;
    if (i >= total) return;
    int ch = (int)(i % c);
    float inv_n = 1.f / (float)n;
    float mu  = stats[ch] * inv_n;
    float var = stats[c + ch] * inv_n - mu * mu;
    float v = gb[ch] * (X[i] - mu) * rsqrtf(var + 1e-5f) + gb[c + ch];
    Y[i] = (v > 0.f) ? v : expm1f(v);
}

__global__ void bn_apply_hh(const __half* __restrict__ X, __half* __restrict__ Y,
                            const float* __restrict__ stats,
                            const float* __restrict__ gb, long long total, int n, int c)
{
    long long i = (long long)blockIdx.x * blockDim.x + threadIdx.x;
    if (i >= total) return;
    int ch = (int)(i % c);
    float inv_n = 1.f / (float)n;
    float mu  = stats[ch] * inv_n;
    float var = stats[c + ch] * inv_n - mu * mu;
    float v = gb[ch] * ((float)X[i] - mu) * rsqrtf(var + 1e-5f) + gb[c + ch];
    v = (v > 0.f) ? v : expm1f(v);
    Y[i] = __float2half(v);
}

__global__ void bn_apply_add(const float* __restrict__ ACC, __half* __restrict__ DST,
                             const int* __restrict__ idx,
                             const float* __restrict__ stats,
                             const float* __restrict__ gb, long long total, int n, int c)
{
    long long i = (long long)blockIdx.x * blockDim.x + threadIdx.x;
    if (i >= total) return;
    int r = (int)(i / c), ch = (int)(i % c);
    float inv_n = 1.f / (float)n;
    float mu  = stats[ch] * inv_n;
    float var = stats[c + ch] * inv_n - mu * mu;
    float v = gb[ch] * (ACC[i] - mu) * rsqrtf(var + 1e-5f) + gb[c + ch];
    v = (v > 0.f) ? v : expm1f(v);
    __half* p = DST + (size_t)idx[r] * c + ch;
    *p = __float2half((float)*p + v);
}

__global__ void scatter_copy_f2h(const float* __restrict__ src, __half* __restrict__ dst,
                                 const int* __restrict__ idx, long long total, int c)
{
    long long i = (long long)blockIdx.x * blockDim.x + threadIdx.x;
    if (i >= total) return;
    int r = (int)(i / c), ch = (int)(i % c);
    dst[(size_t)idx[r] * c + ch] = __float2half(src[i]);
}

// ---------------------------------------------------------------------------
// Host-side orchestration (R12 + surgical memset moves for acc0/acc1)
// ---------------------------------------------------------------------------
static void wh_launch(const float* src, __half* dst, int taps, int cin, int cout,
                      cudaStream_t st)
{
    long long total = (long long)taps * cin * cout;
    build_wh<<<(unsigned)((total + 255) / 256), 256, 0, st>>>(src, dst, total, cin, cout);
}

static void sconv3_launch(const __half* X, const __half* W27, const int* m,
                          int n, int Mpad, int cin, int cout, float* acc,
                          cudaStream_t st, bool do_memset)
{
    if (do_memset)
        cudaMemsetAsync(acc, 0, (size_t)(n + 1) * cout * sizeof(float), st);
    dim3 grid((n + 127) / 128, 27);
    if (cout == 128)
        conv3<128, 2><<<grid, 256, 0, st>>>(X, W27, acc, m, Mpad, n, cin);
    else
        conv3<64, 3><<<grid, 256, 0, st>>>(X, W27, acc, m, Mpad, n, cin);
}

static void tconv_launch(const __half* X, const __half* W8, __half* T,
                         int n, int cin, int cout, cudaStream_t st)
{
    dim3 grid((n + 127) / 128, 8);
    if (cout == 128)
        tconv3<128, 2><<<grid, 256, 0, st>>>(X, W8, T, n, cin);
    else
        tconv3<64, 3><<<grid, 256, 0, st>>>(X, W8, T, n, cin);
}

template<typename T>
static void bn_stats_launch(const T* X, int n, int c, float* stats, cudaStream_t st)
{
    const int rpb = (n >= 16384) ? 128 : 32;
    bn_stats<T><<<(n + rpb - 1) / rpb, c * (256 / c), 0, st>>>(X, n, c, rpb, stats);
}

static void bn_elu_ff(const float* X, float* Y, const float* gb,
                      int n, int c, float* stats, cudaStream_t st)
{
    bn_stats_launch<float>(X, n, c, stats, st);
    long long total = (long long)n * c;
    bn_apply_ff<<<(unsigned)((total + 255) / 256), 256, 0, st>>>(X, Y, stats, gb, total, n, c);
}

static void bn_elu_hh(const __half* X, __half* Y, const float* gb,
                      int n, int c, float* stats, cudaStream_t st)
{
    bn_stats_launch<__half>(X, n, c, stats, st);
    long long total = (long long)n * c;
    bn_apply_hh<<<(unsigned)((total + 255) / 256), 256, 0, st>>>(X, Y, stats, gb, total, n, c);
}

extern "C" void kernel_launch(void* const* d_in, const int* in_sizes, int n_in,
                              void* d_out, int out_size)
{
    const float* feats0 = (const float*)d_in[0];
    const float* feats1 = (const float*)d_in[1];
    const float* feats2 = (const float*)d_in[2];
    const float* w_out0 = (const float*)d_in[3];
    const float* w_out1 = (const float*)d_in[4];
    const float* w_out2 = (const float*)d_in[5];
    const float* wt2    = (const float*)d_in[6];
    const float* wu2    = (const float*)d_in[7];
    const float* wt1    = (const float*)d_in[8];
    const float* wu1    = (const float*)d_in[9];
    const float* bn_out0 = (const float*)d_in[10];
    const float* bn_out1 = (const float*)d_in[11];
    const float* bn_out2 = (const float*)d_in[12];
    const float* bn_up2a = (const float*)d_in[13];
    const float* bn_up2b = (const float*)d_in[14];
    const float* bn_up1a = (const float*)d_in[15];
    const float* bn_up1b = (const float*)d_in[16];
    const int* m_c2 = (const int*)d_in[19];
    const int* m_g2 = (const int*)d_in[20];
    const int* m_u1 = (const int*)d_in[21];
    const int* m_g1 = (const int*)d_in[22];
    const int* m_u0 = (const int*)d_in[23];
    const int* lat1_idx = (const int*)d_in[24];
    const int* up1_idx  = (const int*)d_in[25];
    const int* lat0_idx = (const int*)d_in[26];
    const int* up0_idx  = (const int*)d_in[27];

    const int N0 = in_sizes[0] / 64;
    const int N1 = in_sizes[1] / 128;
    const int N2 = in_sizes[2] / 256;
    const int U1 = in_sizes[17] / 128;
    const int U0 = in_sizes[18] / 64;
    const int Mc2 = in_sizes[19] / 52;
    const int Mg2 = in_sizes[20] / 52;
    const int Mu1 = in_sizes[21] / 52;
    const int Mg1 = in_sizes[22] / 52;
    const int Mu0 = in_sizes[23] / 52;
    const int G2 = 8 * N2;
    const int G1 = 8 * U1;

    float *acc2, *accg2, *acc1, *accg1, *acc0, *stats;
    __half *f2hbuf, *tg2h, *x1h, *t1h, *x0h, *wh;
    cudaGetSymbolAddress((void**)&acc2,  g_acc2);
    cudaGetSymbolAddress((void**)&accg2, g_accg2);
    cudaGetSymbolAddress((void**)&acc1,  g_acc1);
    cudaGetSymbolAddress((void**)&accg1, g_accg1);
    cudaGetSymbolAddress((void**)&acc0,  g_acc0);
    cudaGetSymbolAddress((void**)&stats, g_stats);
    cudaGetSymbolAddress((void**)&f2hbuf, g_f2h);
    cudaGetSymbolAddress((void**)&tg2h,  g_tg2h);
    cudaGetSymbolAddress((void**)&x1h,   g_x1h);
    cudaGetSymbolAddress((void**)&t1h,   g_t1h);
    cudaGetSymbolAddress((void**)&x0h,   g_x0h);
    cudaGetSymbolAddress((void**)&wh,    g_wh);

    float* out0 = (float*)d_out;
    float* out1 = out0 + (size_t)U0 * 128;
    float* out2 = out1 + (size_t)U1 * 128;

    static cudaStream_t s1 = nullptr;
    static cudaEvent_t eRoot = nullptr, eF2 = nullptr, eX1 = nullptr, eEnd = nullptr;
    if (!s1) {
        cudaStreamCreateWithFlags(&s1, cudaStreamNonBlocking);
        cudaEventCreateWithFlags(&eRoot, cudaEventDisableTiming);
        cudaEventCreateWithFlags(&eF2,   cudaEventDisableTiming);
        cudaEventCreateWithFlags(&eX1,   cudaEventDisableTiming);
        cudaEventCreateWithFlags(&eEnd,  cudaEventDisableTiming);
    }
    cudaStream_t s0 = 0;

    // zero all bn-stats slots once
    cudaMemsetAsync(stats, 0, 8 * 256 * sizeof(float), s0);

    // ---- fork ----
    cudaEventRecord(eRoot, s0);
    cudaStreamWaitEvent(s1, eRoot, 0);

    // ===== s0: feats2 fp16 + w_out2, then out2 head =====
    {
        long long t = (long long)N2 * 256;
        f2h<<<(unsigned)((t + 255) / 256), 256, 0, s0>>>(feats2, f2hbuf, t);
    }
    cudaEventRecord(eF2, s0);
    wh_launch(w_out2, wh + O_WOUT2, 27, 256, 128, s0);
    sconv3_launch(f2hbuf, wh + O_WOUT2, m_c2, N2, Mc2, 256, 128, acc2, s0, true);
    bn_elu_ff(acc2, out2, bn_out2, N2, 128, stats + 0*256, s0);
    wh_launch(w_out1, wh + O_WOUT1, 27, 128, 128, s0);
    // acc1 memset hoisted here: overlaps s1's up-block-2 work, before eX1 wait
    cudaMemsetAsync(acc1, 0, (size_t)(U1 + 1) * 128 * sizeof(float), s0);

    // ===== s1: acc0 memset (hoisted off critical tail) + weights + union bases =====
    cudaMemsetAsync(acc0, 0, (size_t)(U0 + 1) * 128 * sizeof(float), s1);
    wh_launch(wt2, wh + O_WT2, 8, 256, 128, s1);
    wh_launch(wu2, wh + O_WU2, 27, 128, 128, s1);
    wh_launch(wt1, wh + O_WT1, 8, 128, 64, s1);
    wh_launch(wu1, wh + O_WU1, 27, 64, 64, s1);
    wh_launch(w_out0, wh + O_WOUT0, 27, 64, 128, s1);

    cudaMemsetAsync(x1h, 0, (size_t)U1 * 128 * sizeof(__half), s1);
    {
        long long t = (long long)N1 * 128;
        scatter_copy_f2h<<<(unsigned)((t + 255) / 256), 256, 0, s1>>>(feats1, x1h, lat1_idx, t, 128);
    }
    cudaMemsetAsync(x0h, 0, (size_t)U0 * 64 * sizeof(__half), s1);
    {
        long long t = (long long)N0 * 64;
        scatter_copy_f2h<<<(unsigned)((t + 255) / 256), 256, 0, s1>>>(feats0, x0h, lat0_idx, t, 64);
    }

    // up block 2 (needs f2hbuf from s0)
    cudaStreamWaitEvent(s1, eF2, 0);
    tconv_launch(f2hbuf, wh + O_WT2, tg2h, N2, 256, 128, s1);
    bn_elu_hh(tg2h, tg2h, bn_up2a, G2, 128, stats + 1*256, s1);
    sconv3_launch(tg2h, wh + O_WU2, m_g2, G2, Mg2, 128, 128, accg2, s1, true);
    bn_stats_launch<float>(accg2, G2, 128, stats + 2*256, s1);
    {
        long long t = (long long)G2 * 128;
        bn_apply_add<<<(unsigned)((t + 255) / 256), 256, 0, s1>>>(
            accg2, x1h, up1_idx, stats + 2*256, bn_up2b, t, G2, 128);
    }
    cudaEventRecord(eX1, s1);

    // up block 1
    tconv_launch(x1h, wh + O_WT1, t1h, U1, 128, 64, s1);
    bn_elu_hh(t1h, t1h, bn_up1a, G1, 64, stats + 3*256, s1);
    sconv3_launch(t1h, wh + O_WU1, m_g1, G1, Mg1, 64, 64, accg1, s1, true);
    bn_stats_launch<float>(accg1, G1, 64, stats + 4*256, s1);
    {
        long long t = (long long)G1 * 64;
        bn_apply_add<<<(unsigned)((t + 255) / 256), 256, 0, s1>>>(
            accg1, x0h, up0_idx, stats + 4*256, bn_up1b, t, G1, 64);
    }
    // out0 head (acc0 pre-zeroed at s1 head)
    sconv3_launch(x0h, wh + O_WOUT0, m_u0, U0, Mu0, 64, 128, acc0, s1, false);
    bn_elu_ff(acc0, out0, bn_out0, U0, 128, stats + 5*256, s1);
    cudaEventRecord(eEnd, s1);

    // ===== s0: out1 head, overlapping up-block-1 (acc1 pre-zeroed above) =====
    cudaStreamWaitEvent(s0, eX1, 0);
    sconv3_launch(x1h, wh + O_WOUT1, m_u1, U1, Mu1, 128, 128, acc1, s0, false);
    bn_elu_ff(acc1, out1, bn_out1, U1, 128, stats + 6*256, s0);

    // ---- join ----
    cudaStreamWaitEvent(s0, eEnd, 0);
}

// round 16
// speedup vs baseline: 1.1593x; 1.0135x over previous
#include <cuda_runtime.h>
#include <cuda_fp16.h>
#include <math.h>

// ---------------------------------------------------------------------------
// Static scratch (allocation-free per harness rules)
// ---------------------------------------------------------------------------
#define N2MAX 1536
#define G2MAX (8*N2MAX)
#define U1MAX 15872
#define G1MAX (8*U1MAX)
#define U0MAX 160256

__device__ float g_acc2[(N2MAX+1)*128];
__device__ float g_accg2[((size_t)G2MAX+1)*128];
__device__ float g_acc1[((size_t)U1MAX+1)*128];
__device__ float g_accg1[((size_t)G1MAX+1)*64];
__device__ float g_acc0[((size_t)U0MAX+1)*128];
__device__ float g_stats[8*256];

// fp16 GEMM inputs
__device__ __half g_f2h[(size_t)N2MAX*256];
__device__ __half g_tg2h[(size_t)G2MAX*128];
__device__ __half g_x1h[(size_t)U1MAX*128];
__device__ __half g_t1h[(size_t)G1MAX*64];
__device__ __half g_x0h[(size_t)U0MAX*64];
// fp16 weights, n-major [tap][cout][cin]
__device__ __half g_wh[2428928];

#define O_WOUT0 0
#define O_WOUT1 221184
#define O_WOUT2 663552
#define O_WT2   1548288
#define O_WU2   1810432
#define O_WT1   2252800
#define O_WU1   2318336

#define BSTR 40   // sub-chunk row stride in halves (80B): 16B-aligned, ldsm conflict-free

__device__ __forceinline__ unsigned smem_u32(const void* p) {
    unsigned a;
    asm("{ .reg .u64 t; cvta.to.shared.u64 t, %1; cvt.u32.u64 %0, t; }" : "=r"(a) : "l"(p));
    return a;
}
__device__ __forceinline__ void cp_async16z(void* sdst, const void* gsrc, int bytes) {
    unsigned saddr = smem_u32(sdst);
    asm volatile("cp.async.cg.shared.global [%0], [%1], 16, %2;"
                 :: "r"(saddr), "l"(gsrc), "r"(bytes));
}
__device__ __forceinline__ void cp_async16(void* sdst, const void* gsrc) {
    unsigned saddr = smem_u32(sdst);
    asm volatile("cp.async.cg.shared.global [%0], [%1], 16;" :: "r"(saddr), "l"(gsrc));
}
__device__ __forceinline__ void cp_commit() {
    asm volatile("cp.async.commit_group;" ::: "memory");
}
template<int N>
__device__ __forceinline__ void cp_wait() {
    asm volatile("cp.async.wait_group %0;" :: "n"(N) : "memory");
}
__device__ __forceinline__ void ldsm_x4(unsigned& r0, unsigned& r1,
                                        unsigned& r2, unsigned& r3, const void* p)
{
    unsigned addr = smem_u32(p);
    asm volatile("ldmatrix.sync.aligned.m8n8.x4.shared.b16 {%0,%1,%2,%3}, [%4];"
                 : "=r"(r0), "=r"(r1), "=r"(r2), "=r"(r3) : "r"(addr));
}
__device__ __forceinline__ void mma_f16(float& c0, float& c1, float& c2, float& c3,
                                        unsigned a0, unsigned a1, unsigned a2, unsigned a3,
                                        unsigned b0, unsigned b1)
{
    asm volatile("mma.sync.aligned.m16n8k16.row.col.f32.f16.f16.f32 "
                 "{%0,%1,%2,%3},{%4,%5,%6,%7},{%8,%9},{%0,%1,%2,%3};"
                 : "+f"(c0), "+f"(c1), "+f"(c2), "+f"(c3)
                 : "r"(a0), "r"(a1), "r"(a2), "r"(a3), "r"(b0), "r"(b1));
}
__device__ __forceinline__ void red_add_v2(float* p, float a, float b) {
    asm volatile("red.global.add.v2.f32 [%0], {%1,%2};"
                 :: "l"(p), "f"(a), "f"(b) : "memory");
}

// ---------------------------------------------------------------------------
// Pipelined GEMM body: 128 x TN x cin fp16, k sub-chunks of 32, double-buffered
// cp.async groups (wait_group 1 overlaps next chunk load with current MMA).
// ---------------------------------------------------------------------------
template<int TN>
__device__ __forceinline__ void load_sub(
    const __half* asrc, int abytes, const __half* __restrict__ Wt,
    int cin, int ks, __half (*Asm)[BSTR], __half (*Bsm)[BSTR], int tid)
{
    // A: 128 rows x 32 k (4 segs of 8 halves); 2 threads/row x 2 segs
    const int ar  = tid >> 1;
    const int as0 = (tid & 1) * 2;
    #pragma unroll
    for (int j = 0; j < 2; j++) {
        const int seg = as0 + j;
        cp_async16z(&Asm[ar][seg * 8], asrc + ks + seg * 8, abytes);
    }
    // B: TN rows x 4 segs
    #pragma unroll
    for (int l = 0; l < TN / 64; l++) {
        const int idx = tid + l * 256;
        const int nn = idx >> 2, seg = idx & 3;
        cp_async16(&Bsm[nn][seg * 8], Wt + (size_t)nn * cin + ks + seg * 8);
    }
    cp_commit();
}

template<int TN>
__device__ __forceinline__ void mma_sub(const __half (*Asm)[BSTR],
                                        const __half (*Bsm)[BSTR],
                                        int wm, int wn, int lane,
                                        float (&c)[2][TN/16][4])
{
    constexpr int NI = TN / 16;
    const int lr = lane & 15;
    const int koff = (lane >> 4) * 8;
    #pragma unroll
    for (int kt = 0; kt < 2; kt++) {
        const int kb = kt * 16 + koff;
        unsigned a[2][4];
        #pragma unroll
        for (int mi = 0; mi < 2; mi++)
            ldsm_x4(a[mi][0], a[mi][1], a[mi][2], a[mi][3],
                    &Asm[wm + mi * 16 + lr][kb]);
        unsigned b[NI][2];
        #pragma unroll
        for (int nj = 0; nj < NI / 2; nj++) {
            unsigned r0, r1, r2, r3;
            ldsm_x4(r0, r1, r2, r3, &Bsm[wn + nj * 16 + lr][kb]);
            b[2*nj][0] = r0; b[2*nj+1][0] = r1;
            b[2*nj][1] = r2; b[2*nj+1][1] = r3;
        }
        #pragma unroll
        for (int mi = 0; mi < 2; mi++)
            #pragma unroll
            for (int ni = 0; ni < NI; ni++)
                mma_f16(c[mi][ni][0], c[mi][ni][1], c[mi][ni][2], c[mi][ni][3],
                        a[mi][0], a[mi][1], a[mi][2], a[mi][3], b[ni][0], b[ni][1]);
    }
}

template<int TN>
__device__ __forceinline__ void gemm_body(
    const __half* __restrict__ X, const __half* __restrict__ Wt,
    const int* gidx, __half (*Asm)[128][BSTR], __half (*Bsm)[TN][BSTR],
    int cin, int tid, int wm, int wn, int lane, float (&c)[2][TN/16][4])
{
    const int g = gidx[tid >> 1];
    const __half* asrc = X + (size_t)(g >= 0 ? g : 0) * cin;
    const int abytes = (g >= 0) ? 16 : 0;
    const int nch = cin >> 5;

    load_sub<TN>(asrc, abytes, Wt, cin, 0, Asm[0], Bsm[0], tid);
    if (nch > 1) {
        load_sub<TN>(asrc, abytes, Wt, cin, 32, Asm[1], Bsm[1], tid);
        cp_wait<1>();
    } else {
        cp_wait<0>();
    }
    __syncthreads();

    for (int s = 0; s < nch; s++) {
        const int cur = s & 1;
        mma_sub<TN>(Asm[cur], Bsm[cur], wm, wn, lane, c);
        if (s + 1 < nch) {
            __syncthreads();               // all warps done reading buffer cur
            if (s + 2 < nch) {
                load_sub<TN>(asrc, abytes, Wt, cin, (s + 2) * 32,
                             Asm[cur], Bsm[cur], tid);
                cp_wait<1>();              // chunk s+1 ready, s+2 in flight
            } else {
                cp_wait<0>();
            }
            __syncthreads();
        }
    }
}

// ---------------------------------------------------------------------------
// Scatter-style tap conv (fp16 HMMA + fp32 RED). grid = (ceil(n/128), 27)
// ---------------------------------------------------------------------------
template<int TN, int MAXCTA>
__global__ __launch_bounds__(256, MAXCTA) void conv3(
    const __half* __restrict__ X, const __half* __restrict__ W27,
    float* __restrict__ C, const int* __restrict__ maps,
    int Mpad, int n, int cin)
{
    constexpr int NI = TN / 16;
    __shared__ __align__(16) __half Asm[2][128][BSTR];
    __shared__ __align__(16) __half Bsm[2][TN][BSTR];
    __shared__ int gidx[128], sidx[128];

    const int z    = blockIdx.y;
    const int Mz   = (z == 26) ? n : Mpad;
    const int row0 = blockIdx.x * 128;
    if (row0 >= Mz) return;

    const int tap  = (z == 26) ? 13 : ((z < 13) ? z : z + 1);
    const __half* Wt = W27 + (size_t)tap * cin * TN;
    const int tid  = threadIdx.x;
    const int scrap = n;

    int myvalid = 0;
    if (tid < 128) {
        int r = row0 + tid;
        int g = -1, s = -1;
        if (r < Mz) {
            if (z == 26) { g = r; s = r; }
            else {
                g = maps[(size_t)z * Mpad + r];
                s = maps[(size_t)(26 + z) * Mpad + r];
            }
        }
        gidx[tid] = g;
        sidx[tid] = s;
        myvalid = (s >= 0 && s != scrap);
    }
    if (__syncthreads_count(myvalid) == 0) return;

    const int lane = tid & 31;
    const int warp = tid >> 5;
    const int wm = (warp & 3) * 32;
    const int wn = (warp >> 2) * (TN / 2);

    float c[2][NI][4];
    #pragma unroll
    for (int mi = 0; mi < 2; mi++)
        #pragma unroll
        for (int ni = 0; ni < NI; ni++)
            #pragma unroll
            for (int j = 0; j < 4; j++) c[mi][ni][j] = 0.f;

    gemm_body<TN>(X, Wt, gidx, Asm, Bsm, cin, tid, wm, wn, lane, c);

    const int qr = lane >> 2, qc = lane & 3;
    #pragma unroll
    for (int mi = 0; mi < 2; mi++) {
        #pragma unroll
        for (int half_ = 0; half_ < 2; half_++) {
            const int lr2 = wm + mi * 16 + qr + half_ * 8;
            const int o = sidx[lr2];
            if (o < 0 || o == scrap) continue;
            float* cp = C + (size_t)o * TN + wn + qc * 2;
            #pragma unroll
            for (int ni = 0; ni < NI; ni++)
                red_add_v2(cp + ni * 8, c[mi][ni][half_*2], c[mi][ni][half_*2+1]);
        }
    }
}

// ---------------------------------------------------------------------------
// Batched transpose conv (fp16 in, fp16 out): T[z*n + r] = X[r] @ Wt[z]
// ---------------------------------------------------------------------------
template<int TN, int MAXCTA>
__global__ __launch_bounds__(256, MAXCTA) void tconv3(
    const __half* __restrict__ X, const __half* __restrict__ W8,
    __half* __restrict__ T, int n, int cin)
{
    constexpr int NI = TN / 16;
    __shared__ __align__(16) __half Asm[2][128][BSTR];
    __shared__ __align__(16) __half Bsm[2][TN][BSTR];
    __shared__ int gidx[128];

    const int z    = blockIdx.y;
    const int row0 = blockIdx.x * 128;
    if (row0 >= n) return;
    const __half* Wt = W8 + (size_t)z * cin * TN;
    const int tid  = threadIdx.x;

    if (tid < 128) {
        int r = row0 + tid;
        gidx[tid] = (r < n) ? r : -1;
    }
    __syncthreads();

    const int lane = tid & 31;
    const int warp = tid >> 5;
    const int wm = (warp & 3) * 32;
    const int wn = (warp >> 2) * (TN / 2);

    float c[2][NI][4];
    #pragma unroll
    for (int mi = 0; mi < 2; mi++)
        #pragma unroll
        for (int ni = 0; ni < NI; ni++)
            #pragma unroll
            for (int j = 0; j < 4; j++) c[mi][ni][j] = 0.f;

    gemm_body<TN>(X, Wt, gidx, Asm, Bsm, cin, tid, wm, wn, lane, c);

    const int qr = lane >> 2, qc = lane & 3;
    #pragma unroll
    for (int mi = 0; mi < 2; mi++) {
        #pragma unroll
        for (int half_ = 0; half_ < 2; half_++) {
            const int r = row0 + wm + mi * 16 + qr + half_ * 8;
            if (r >= n) continue;
            __half* tp = T + ((size_t)z * n + r) * TN + wn + qc * 2;
            #pragma unroll
            for (int ni = 0; ni < NI; ni++) {
                __half2 hv = __floats2half2_rn(c[mi][ni][half_*2], c[mi][ni][half_*2+1]);
                *reinterpret_cast<__half2*>(tp + ni * 8) = hv;
            }
        }
    }
}

// ---------------------------------------------------------------------------
// One-shot converters (scalar, proven)
// ---------------------------------------------------------------------------
__global__ void build_wh(const float* __restrict__ src, __half* __restrict__ dst,
                         long long total, int cin, int cout)
{
    long long i = (long long)blockIdx.x * blockDim.x + threadIdx.x;
    if (i >= total) return;
    const long long per = (long long)cin * cout;
    const int t = (int)(i / per);
    const int rem = (int)(i % per);
    const int k = rem / cout, nn = rem % cout;
    dst[(long long)t * per + (long long)nn * cin + k] = __float2half(src[i]);
}

__global__ void f2h(const float* __restrict__ src, __half* __restrict__ dst, long long n)
{
    long long i = (long long)blockIdx.x * blockDim.x + threadIdx.x;
    if (i >= n) return;
    dst[i] = __float2half(src[i]);
}

// ---------------------------------------------------------------------------
// BatchNorm (training-mode batch stats) + ELU (scalar, proven)
// ---------------------------------------------------------------------------
template<typename T>
__global__ void bn_stats(const T* __restrict__ X, int n, int c, int rpb,
                         float* __restrict__ stats)
{
    const int tpr = blockDim.x / c;
    const int ch = threadIdx.x % c;
    const int rg = threadIdx.x / c;
    const int r0 = blockIdx.x * rpb;
    int rend = r0 + rpb; if (rend > n) rend = n;
    float s = 0.f, sq = 0.f;
    for (int r = r0 + rg; r < rend; r += tpr) {
        float v = (float)X[(size_t)r * c + ch];
        s += v; sq += v * v;
    }
    atomicAdd(&stats[ch], s);
    atomicAdd(&stats[c + ch], sq);
}

__global__ void bn_apply_ff(const float* __restrict__ X, float* __restrict__ Y,
                            const float* __restrict__ stats,
                            const float* __restrict__ gb, long long total, int n, int c)
{
    long long i = (long long)blockIdx.x * blockDim.x + threadIdx.x;
    if (i >= total) return;
    int ch = (int)(i % c);
    float inv_n = 1.f / (float)n;
    float mu  = stats[ch] * inv_n;
    float var = stats[c + ch] * inv_n - mu * mu;
    float v = gb[ch] * (X[i] - mu) * rsqrtf(var + 1e-5f) + gb[c + ch];
    Y[i] = (v > 0.f) ? v : expm1f(v);
}

__global__ void bn_apply_hh(const __half* __restrict__ X, __half* __restrict__ Y,
                            const float* __restrict__ stats,
                            const float* __restrict__ gb, long long total, int n, int c)
{
    long long i = (long long)blockIdx.x * blockDim.x + threadIdx.x;
    if (i >= total) return;
    int ch = (int)(i % c);
    float inv_n = 1.f / (float)n;
    float mu  = stats[ch] * inv_n;
    float var = stats[c + ch] * inv_n - mu * mu;
    float v = gb[ch] * ((float)X[i] - mu) * rsqrtf(var + 1e-5f) + gb[c + ch];
    v = (v > 0.f) ? v : expm1f(v);
    Y[i] = __float2half(v);
}

__global__ void bn_apply_add(const float* __restrict__ ACC, __half* __restrict__ DST,
                             const int* __restrict__ idx,
                             const float* __restrict__ stats,
                             const float* __restrict__ gb, long long total, int n, int c)
{
    long long i = (long long)blockIdx.x * blockDim.x + threadIdx.x;
    if (i >= total) return;
    int r = (int)(i / c), ch = (int)(i % c);
    float inv_n = 1.f / (float)n;
    float mu  = stats[ch] * inv_n;
    float var = stats[c + ch] * inv_n - mu * mu;
    float v = gb[ch] * (ACC[i] - mu) * rsqrtf(var + 1e-5f) + gb[c + ch];
    v = (v > 0.f) ? v : expm1f(v);
    __half* p = DST + (size_t)idx[r] * c + ch;
    *p = __float2half((float)*p + v);
}

__global__ void scatter_copy_f2h(const float* __restrict__ src, __half* __restrict__ dst,
                                 const int* __restrict__ idx, long long total, int c)
{
    long long i = (long long)blockIdx.x * blockDim.x + threadIdx.x;
    if (i >= total) return;
    int r = (int)(i / c), ch = (int)(i % c);
    dst[(size_t)idx[r] * c + ch] = __float2half(src[i]);
}

// ---------------------------------------------------------------------------
// Host-side orchestration (exact R15 schedule)
// ---------------------------------------------------------------------------
static void wh_launch(const float* src, __half* dst, int taps, int cin, int cout,
                      cudaStream_t st)
{
    long long total = (long long)taps * cin * cout;
    build_wh<<<(unsigned)((total + 255) / 256), 256, 0, st>>>(src, dst, total, cin, cout);
}

static void sconv3_launch(const __half* X, const __half* W27, const int* m,
                          int n, int Mpad, int cin, int cout, float* acc,
                          cudaStream_t st, bool do_memset)
{
    if (do_memset)
        cudaMemsetAsync(acc, 0, (size_t)(n + 1) * cout * sizeof(float), st);
    dim3 grid((n + 127) / 128, 27);
    if (cout == 128)
        conv3<128, 2><<<grid, 256, 0, st>>>(X, W27, acc, m, Mpad, n, cin);
    else
        conv3<64, 3><<<grid, 256, 0, st>>>(X, W27, acc, m, Mpad, n, cin);
}

static void tconv_launch(const __half* X, const __half* W8, __half* T,
                         int n, int cin, int cout, cudaStream_t st)
{
    dim3 grid((n + 127) / 128, 8);
    if (cout == 128)
        tconv3<128, 2><<<grid, 256, 0, st>>>(X, W8, T, n, cin);
    else
        tconv3<64, 3><<<grid, 256, 0, st>>>(X, W8, T, n, cin);
}

template<typename T>
static void bn_stats_launch(const T* X, int n, int c, float* stats, cudaStream_t st)
{
    const int rpb = (n >= 16384) ? 128 : 32;
    bn_stats<T><<<(n + rpb - 1) / rpb, c * (256 / c), 0, st>>>(X, n, c, rpb, stats);
}

static void bn_elu_ff(const float* X, float* Y, const float* gb,
                      int n, int c, float* stats, cudaStream_t st)
{
    bn_stats_launch<float>(X, n, c, stats, st);
    long long total = (long long)n * c;
    bn_apply_ff<<<(unsigned)((total + 255) / 256), 256, 0, st>>>(X, Y, stats, gb, total, n, c);
}

static void bn_elu_hh(const __half* X, __half* Y, const float* gb,
                      int n, int c, float* stats, cudaStream_t st)
{
    bn_stats_launch<__half>(X, n, c, stats, st);
    long long total = (long long)n * c;
    bn_apply_hh<<<(unsigned)((total + 255) / 256), 256, 0, st>>>(X, Y, stats, gb, total, n, c);
}

extern "C" void kernel_launch(void* const* d_in, const int* in_sizes, int n_in,
                              void* d_out, int out_size)
{
    const float* feats0 = (const float*)d_in[0];
    const float* feats1 = (const float*)d_in[1];
    const float* feats2 = (const float*)d_in[2];
    const float* w_out0 = (const float*)d_in[3];
    const float* w_out1 = (const float*)d_in[4];
    const float* w_out2 = (const float*)d_in[5];
    const float* wt2    = (const float*)d_in[6];
    const float* wu2    = (const float*)d_in[7];
    const float* wt1    = (const float*)d_in[8];
    const float* wu1    = (const float*)d_in[9];
    const float* bn_out0 = (const float*)d_in[10];
    const float* bn_out1 = (const float*)d_in[11];
    const float* bn_out2 = (const float*)d_in[12];
    const float* bn_up2a = (const float*)d_in[13];
    const float* bn_up2b = (const float*)d_in[14];
    const float* bn_up1a = (const float*)d_in[15];
    const float* bn_up1b = (const float*)d_in[16];
    const int* m_c2 = (const int*)d_in[19];
    const int* m_g2 = (const int*)d_in[20];
    const int* m_u1 = (const int*)d_in[21];
    const int* m_g1 = (const int*)d_in[22];
    const int* m_u0 = (const int*)d_in[23];
    const int* lat1_idx = (const int*)d_in[24];
    const int* up1_idx  = (const int*)d_in[25];
    const int* lat0_idx = (const int*)d_in[26];
    const int* up0_idx  = (const int*)d_in[27];

    const int N0 = in_sizes[0] / 64;
    const int N1 = in_sizes[1] / 128;
    const int N2 = in_sizes[2] / 256;
    const int U1 = in_sizes[17] / 128;
    const int U0 = in_sizes[18] / 64;
    const int Mc2 = in_sizes[19] / 52;
    const int Mg2 = in_sizes[20] / 52;
    const int Mu1 = in_sizes[21] / 52;
    const int Mg1 = in_sizes[22] / 52;
    const int Mu0 = in_sizes[23] / 52;
    const int G2 = 8 * N2;
    const int G1 = 8 * U1;

    float *acc2, *accg2, *acc1, *accg1, *acc0, *stats;
    __half *f2hbuf, *tg2h, *x1h, *t1h, *x0h, *wh;
    cudaGetSymbolAddress((void**)&acc2,  g_acc2);
    cudaGetSymbolAddress((void**)&accg2, g_accg2);
    cudaGetSymbolAddress((void**)&acc1,  g_acc1);
    cudaGetSymbolAddress((void**)&accg1, g_accg1);
    cudaGetSymbolAddress((void**)&acc0,  g_acc0);
    cudaGetSymbolAddress((void**)&stats, g_stats);
    cudaGetSymbolAddress((void**)&f2hbuf, g_f2h);
    cudaGetSymbolAddress((void**)&tg2h,  g_tg2h);
    cudaGetSymbolAddress((void**)&x1h,   g_x1h);
    cudaGetSymbolAddress((void**)&t1h,   g_t1h);
    cudaGetSymbolAddress((void**)&x0h,   g_x0h);
    cudaGetSymbolAddress((void**)&wh,    g_wh);

    float* out0 = (float*)d_out;
    float* out1 = out0 + (size_t)U0 * 128;
    float* out2 = out1 + (size_t)U1 * 128;

    static cudaStream_t s1 = nullptr;
    static cudaEvent_t eRoot = nullptr, eF2 = nullptr, eX1 = nullptr, eEnd = nullptr;
    if (!s1) {
        cudaStreamCreateWithFlags(&s1, cudaStreamNonBlocking);
        cudaEventCreateWithFlags(&eRoot, cudaEventDisableTiming);
        cudaEventCreateWithFlags(&eF2,   cudaEventDisableTiming);
        cudaEventCreateWithFlags(&eX1,   cudaEventDisableTiming);
        cudaEventCreateWithFlags(&eEnd,  cudaEventDisableTiming);
    }
    cudaStream_t s0 = 0;

    // zero all bn-stats slots once
    cudaMemsetAsync(stats, 0, 8 * 256 * sizeof(float), s0);

    // ---- fork ----
    cudaEventRecord(eRoot, s0);
    cudaStreamWaitEvent(s1, eRoot, 0);

    // ===== s0: feats2 fp16 + w_out2, then out2 head =====
    {
        long long t = (long long)N2 * 256;
        f2h<<<(unsigned)((t + 255) / 256), 256, 0, s0>>>(feats2, f2hbuf, t);
    }
    cudaEventRecord(eF2, s0);
    wh_launch(w_out2, wh + O_WOUT2, 27, 256, 128, s0);
    sconv3_launch(f2hbuf, wh + O_WOUT2, m_c2, N2, Mc2, 256, 128, acc2, s0, true);
    bn_elu_ff(acc2, out2, bn_out2, N2, 128, stats + 0*256, s0);
    wh_launch(w_out1, wh + O_WOUT1, 27, 128, 128, s0);
    // acc1 memset hoisted: overlaps s1's up-block-2 work, before eX1 wait
    cudaMemsetAsync(acc1, 0, (size_t)(U1 + 1) * 128 * sizeof(float), s0);

    // ===== s1: acc0 memset (hoisted) + weights + union bases =====
    cudaMemsetAsync(acc0, 0, (size_t)(U0 + 1) * 128 * sizeof(float), s1);
    wh_launch(wt2, wh + O_WT2, 8, 256, 128, s1);
    wh_launch(wu2, wh + O_WU2, 27, 128, 128, s1);
    wh_launch(wt1, wh + O_WT1, 8, 128, 64, s1);
    wh_launch(wu1, wh + O_WU1, 27, 64, 64, s1);
    wh_launch(w_out0, wh + O_WOUT0, 27, 64, 128, s1);

    cudaMemsetAsync(x1h, 0, (size_t)U1 * 128 * sizeof(__half), s1);
    {
        long long t = (long long)N1 * 128;
        scatter_copy_f2h<<<(unsigned)((t + 255) / 256), 256, 0, s1>>>(feats1, x1h, lat1_idx, t, 128);
    }
    cudaMemsetAsync(x0h, 0, (size_t)U0 * 64 * sizeof(__half), s1);
    {
        long long t = (long long)N0 * 64;
        scatter_copy_f2h<<<(unsigned)((t + 255) / 256), 256, 0, s1>>>(feats0, x0h, lat0_idx, t, 64);
    }

    // up block 2 (needs f2hbuf from s0)
    cudaStreamWaitEvent(s1, eF2, 0);
    tconv_launch(f2hbuf, wh + O_WT2, tg2h, N2, 256, 128, s1);
    bn_elu_hh(tg2h, tg2h, bn_up2a, G2, 128, stats + 1*256, s1);
    sconv3_launch(tg2h, wh + O_WU2, m_g2, G2, Mg2, 128, 128, accg2, s1, true);
    bn_stats_launch<float>(accg2, G2, 128, stats + 2*256, s1);
    {
        long long t = (long long)G2 * 128;
        bn_apply_add<<<(unsigned)((t + 255) / 256), 256, 0, s1>>>(
            accg2, x1h, up1_idx, stats + 2*256, bn_up2b, t, G2, 128);
    }
    cudaEventRecord(eX1, s1);

    // up block 1
    tconv_launch(x1h, wh + O_WT1, t1h, U1, 128, 64, s1);
    bn_elu_hh(t1h, t1h, bn_up1a, G1, 64, stats + 3*256, s1);
    sconv3_launch(t1h, wh + O_WU1, m_g1, G1, Mg1, 64, 64, accg1, s1, true);
    bn_stats_launch<float>(accg1, G1, 64, stats + 4*256, s1);
    {
        long long t = (long long)G1 * 64;
        bn_apply_add<<<(unsigned)((t + 255) / 256), 256, 0, s1>>>(
            accg1, x0h, up0_idx, stats + 4*256, bn_up1b, t, G1, 64);
    }
    // out0 head (acc0 pre-zeroed at s1 head)
    sconv3_launch(x0h, wh + O_WOUT0, m_u0, U0, Mu0, 64, 128, acc0, s1, false);
    bn_elu_ff(acc0, out0, bn_out0, U0, 128, stats + 5*256, s1);
    cudaEventRecord(eEnd, s1);

    // ===== s0: out1 head, overlapping up-block-1 (acc1 pre-zeroed above) =====
    cudaStreamWaitEvent(s0, eX1, 0);
    sconv3_launch(x1h, wh + O_WOUT1, m_u1, U1, Mu1, 128, 128, acc1, s0, false);
    bn_elu_ff(acc1, out1, bn_out1, U1, 128, stats + 6*256, s0);

    // ---- join ----
    cudaStreamWaitEvent(s0, eEnd, 0);
}